// round 4
// baseline (speedup 1.0000x reference)
#include <cuda_runtime.h>
#include <cuda_bf16.h>
#include <cstdint>
#include <math.h>

#define NN 50000
#define EE 500000
#define ETOT (EE + NN)
#define CC 256
#define DD 128

// ---------------- scratch (static __device__, no allocation) ----------------
__device__ float g_h[(size_t)NN * CC];           // transformed features (fp32)
__device__ __nv_bfloat16 g_ahi[(size_t)NN * CC]; // split-bf16 A (hi)
__device__ __nv_bfloat16 g_alo[(size_t)NN * CC]; // split-bf16 A (lo)
__device__ __nv_bfloat16 g_w1hi[256 * 128], g_w1lo[256 * 128];
__device__ __nv_bfloat16 g_w2hi[256 * 256], g_w2lo[256 * 256];
__device__ float g_esp[2 * NN];   // e_src partials (per column-slice)
__device__ float g_edp[2 * NN];   // e_dst partials
__device__ int   g_deg[NN];
__device__ int   g_rowptr[NN + 1];
__device__ int   g_cursor[NN];
__device__ int   g_col[ETOT];

// ---------------- helpers ----------------
__device__ __forceinline__ uint32_t smem_u32(const void* p) {
    uint32_t a;
    asm("{ .reg .u64 t; cvta.to.shared.u64 t, %1; cvt.u32.u64 %0, t; }"
        : "=r"(a) : "l"(p));
    return a;
}

#define LDSM4(R, addr) \
    asm volatile("ldmatrix.sync.aligned.m8n8.x4.shared.b16 {%0,%1,%2,%3}, [%4];" \
                 : "=r"((R)[0]), "=r"((R)[1]), "=r"((R)[2]), "=r"((R)[3]) \
                 : "r"(addr))

#define MMA_BF16(d, a, b0, b1) \
    asm volatile("mma.sync.aligned.m16n8k16.row.col.f32.bf16.bf16.f32 " \
                 "{%0,%1,%2,%3},{%4,%5,%6,%7},{%8,%9},{%0,%1,%2,%3};" \
                 : "+f"((d)[0]), "+f"((d)[1]), "+f"((d)[2]), "+f"((d)[3]) \
                 : "r"((a)[0]), "r"((a)[1]), "r"((a)[2]), "r"((a)[3]), \
                   "r"(b0), "r"(b1))

// ---------------- prep: split-bf16 conversion + deg zero (fused) ----------------
__global__ void prep_kernel(const float* __restrict__ x,
                            const float* __restrict__ W1,
                            const float* __restrict__ W2) {
    int i = blockIdx.x * blockDim.x + threadIdx.x;
    if (i < NN * DD) {
        float v = x[i];
        __nv_bfloat16 h = __float2bfloat16(v);
        g_ahi[i] = h;
        g_alo[i] = __float2bfloat16(v - __bfloat162float(h));
    }
    if (i < 256 * 128) {
        float v = W1[i];
        __nv_bfloat16 h = __float2bfloat16(v);
        g_w1hi[i] = h;
        g_w1lo[i] = __float2bfloat16(v - __bfloat162float(h));
    }
    if (i < 256 * 256) {
        float v = W2[i];
        __nv_bfloat16 h = __float2bfloat16(v);
        g_w2hi[i] = h;
        g_w2lo[i] = __float2bfloat16(v - __bfloat162float(h));
    }
    if (i < NN) g_deg[i] = 0;
}

// ---------------- CSR build ----------------
__global__ void count_deg_kernel(const int* __restrict__ ei) {
    int i = blockIdx.x * blockDim.x + threadIdx.x;
    if (i >= ETOT) return;
    int d = (i < EE) ? ei[EE + i] : (i - EE);
    atomicAdd(&g_deg[d], 1);
}

// single-block scan: 1024 threads x 49 elems each
__global__ void scan_kernel() {
    __shared__ int sh[1024];
    const int PER = 49;
    int t = threadIdx.x;
    int base = t * PER;
    int s = 0;
    for (int k = 0; k < PER; k++) {
        int i = base + k;
        if (i < NN) s += g_deg[i];
    }
    sh[t] = s;
    __syncthreads();
    for (int off = 1; off < 1024; off <<= 1) {
        int v = (t >= off) ? sh[t - off] : 0;
        __syncthreads();
        sh[t] += v;
        __syncthreads();
    }
    int run = sh[t] - s;   // exclusive prefix
    for (int k = 0; k < PER; k++) {
        int i = base + k;
        if (i < NN) {
            g_rowptr[i] = run;
            g_cursor[i] = run;
            run += g_deg[i];
        }
    }
    if (t == 1023) g_rowptr[NN] = sh[1023];
}

__global__ void fill_kernel(const int* __restrict__ ei) {
    int i = blockIdx.x * blockDim.x + threadIdx.x;
    if (i >= ETOT) return;
    int s, d;
    if (i < EE) { s = ei[i]; d = ei[EE + i]; }
    else        { s = i - EE; d = s; }
    int pos = atomicAdd(&g_cursor[d], 1);
    g_col[pos] = s;
}

// ---------------- HMMA GEMM + fused attention dots epilogue ----------------
// g_h[M,256] = A[M,K]*W[256,K]^T; BM=128, BN=128, BK=32; 8 warps (2m x 4n).
// Split-bf16: acc += Ahi*Whi + Ahi*Wlo + Alo*Whi (fp32 accum).
// Epilogue also computes per-slice partial dots h·a_src, h·a_dst.
#define SST 40   // smem row stride (bf16) — conflict-free for ldmatrix

template <int K, int LAYER>
__global__ __launch_bounds__(256) void mma_gemm_kernel(const float* __restrict__ a_src,
                                                       const float* __restrict__ a_dst) {
    __shared__ __align__(16) __nv_bfloat16 sA[2][128 * SST];
    __shared__ __align__(16) __nv_bfloat16 sB[2][128 * SST];
    __shared__ float sas[128], sad[128], sds[128], sdd[128];

    const __nv_bfloat16* __restrict__ Ahi = g_ahi;
    const __nv_bfloat16* __restrict__ Alo = g_alo;
    const __nv_bfloat16* __restrict__ Whi = (LAYER == 1) ? g_w1hi : g_w2hi;
    const __nv_bfloat16* __restrict__ Wlo = (LAYER == 1) ? g_w1lo : g_w2lo;

    int tid = threadIdx.x;
    int wid = tid >> 5;
    int lane = tid & 31;
    int bm = blockIdx.x * 128;
    int bn = blockIdx.y * 128;
    int ny = blockIdx.y;
    int wm = (wid & 1) * 64;
    int wn = (wid >> 1) * 32;

    if (tid < 128) {
        sas[tid] = a_src[bn + tid];
        sad[tid] = a_dst[bn + tid];
        sds[tid] = 0.f;
        sdd[tid] = 0.f;
    }

    float acc[4][4][4];
    #pragma unroll
    for (int a = 0; a < 4; a++)
        #pragma unroll
        for (int b = 0; b < 4; b++)
            #pragma unroll
            for (int c = 0; c < 4; c++) acc[a][b][c] = 0.f;

    uint32_t aHb = smem_u32(&sA[0][0]);
    uint32_t aLb = smem_u32(&sA[1][0]);
    uint32_t bHb = smem_u32(&sB[0][0]);
    uint32_t bLb = smem_u32(&sB[1][0]);

    int a_row = wm + (lane & 15);
    int a_k8  = (lane >> 4) << 3;
    int b_row = wn + (lane & 7) + ((lane >> 4) << 3);
    int b_k8  = ((lane >> 3) & 1) << 3;

    for (int k0 = 0; k0 < K; k0 += 32) {
        #pragma unroll
        for (int it = 0; it < 2; it++) {
            int idx = tid + it * 256;
            int r = idx >> 2;
            int q = (idx & 3) << 3;
            int row = bm + r;
            uint4 vh = make_uint4(0u, 0u, 0u, 0u);
            uint4 vl = make_uint4(0u, 0u, 0u, 0u);
            if (row < NN) {
                vh = *(const uint4*)&Ahi[(size_t)row * K + k0 + q];
                vl = *(const uint4*)&Alo[(size_t)row * K + k0 + q];
            }
            *(uint4*)&sA[0][r * SST + q] = vh;
            *(uint4*)&sA[1][r * SST + q] = vl;
            *(uint4*)&sB[0][r * SST + q] = *(const uint4*)&Whi[(size_t)(bn + r) * K + k0 + q];
            *(uint4*)&sB[1][r * SST + q] = *(const uint4*)&Wlo[(size_t)(bn + r) * K + k0 + q];
        }
        __syncthreads();

        #pragma unroll
        for (int ks = 0; ks < 2; ks++) {
            int kk = ks * 16;
            uint32_t aH[4][4], aL[4][4], bH[2][4], bL[2][4];
            #pragma unroll
            for (int mt = 0; mt < 4; mt++) {
                uint32_t off = (uint32_t)(((a_row + mt * 16) * SST + kk + a_k8) * 2);
                LDSM4(aH[mt], aHb + off);
                LDSM4(aL[mt], aLb + off);
            }
            #pragma unroll
            for (int bt = 0; bt < 2; bt++) {
                uint32_t off = (uint32_t)(((b_row + bt * 16) * SST + kk + b_k8) * 2);
                LDSM4(bH[bt], bHb + off);
                LDSM4(bL[bt], bLb + off);
            }
            #pragma unroll
            for (int mt = 0; mt < 4; mt++) {
                #pragma unroll
                for (int nt = 0; nt < 4; nt++) {
                    int bt = nt >> 1;
                    int sb = (nt & 1) * 2;
                    MMA_BF16(acc[mt][nt], aH[mt], bH[bt][sb], bH[bt][sb + 1]);
                    MMA_BF16(acc[mt][nt], aH[mt], bL[bt][sb], bL[bt][sb + 1]);
                    MMA_BF16(acc[mt][nt], aL[mt], bH[bt][sb], bH[bt][sb + 1]);
                }
            }
        }
        __syncthreads();
    }

    // ---- epilogue: store g_h + fused partial dots ----
    int gid = lane >> 2;
    int tig = lane & 3;
    #pragma unroll
    for (int mt = 0; mt < 4; mt++) {
        float ds0 = 0.f, ds1 = 0.f, dd0 = 0.f, dd1 = 0.f;
        #pragma unroll
        for (int nt = 0; nt < 4; nt++) {
            int cl = wn + nt * 8 + tig * 2;
            int row0 = bm + wm + mt * 16 + gid;
            int col = bn + cl;
            if (row0 < NN)
                *(float2*)&g_h[(size_t)row0 * CC + col] =
                    make_float2(acc[mt][nt][0], acc[mt][nt][1]);
            int row1 = row0 + 8;
            if (row1 < NN)
                *(float2*)&g_h[(size_t)row1 * CC + col] =
                    make_float2(acc[mt][nt][2], acc[mt][nt][3]);
            float as0 = sas[cl], as1 = sas[cl + 1];
            float ad0 = sad[cl], ad1 = sad[cl + 1];
            ds0 += acc[mt][nt][0] * as0 + acc[mt][nt][1] * as1;
            dd0 += acc[mt][nt][0] * ad0 + acc[mt][nt][1] * ad1;
            ds1 += acc[mt][nt][2] * as0 + acc[mt][nt][3] * as1;
            dd1 += acc[mt][nt][2] * ad0 + acc[mt][nt][3] * ad1;
        }
        #pragma unroll
        for (int o = 1; o <= 2; o <<= 1) {
            ds0 += __shfl_xor_sync(0xFFFFFFFFu, ds0, o);
            ds1 += __shfl_xor_sync(0xFFFFFFFFu, ds1, o);
            dd0 += __shfl_xor_sync(0xFFFFFFFFu, dd0, o);
            dd1 += __shfl_xor_sync(0xFFFFFFFFu, dd1, o);
        }
        if (tig == 0) {
            int lr = wm + mt * 16 + gid;
            atomicAdd(&sds[lr], ds0);
            atomicAdd(&sdd[lr], dd0);
            atomicAdd(&sds[lr + 8], ds1);
            atomicAdd(&sdd[lr + 8], dd1);
        }
    }
    __syncthreads();
    if (tid < 128) {
        int row = bm + tid;
        if (row < NN) {
            g_esp[ny * NN + row] = sds[tid];
            g_edp[ny * NN + row] = sdd[tid];
        }
    }
}

// ---------------- softmax + aggregate: warp per destination node ----------------
// Single pass (e bounded, softmax shift-invariant); software-pipelined gather.
template <bool FIRST>
__global__ void aggregate_kernel(const float* __restrict__ bias,
                                 float* __restrict__ out) {
    int w = (blockIdx.x * blockDim.x + threadIdx.x) >> 5;
    if (w >= NN) return;
    int lane = threadIdx.x & 31;

    float edst = g_edp[w] + g_edp[NN + w];
    int beg = g_rowptr[w];
    int end = g_rowptr[w + 1];

    float sum = 0.f;
    float acc[8] = {0.f, 0.f, 0.f, 0.f, 0.f, 0.f, 0.f, 0.f};

    int sN = g_col[beg];                       // deg >= 1 (self-loop)
    float eN = g_esp[sN] + g_esp[NN + sN];

    for (int j = beg; j < end; j++) {
        int s = sN;
        float es = eN;
        const float4* hp = (const float4*)(g_h + (size_t)s * CC + lane * 8);
        float4 v0 = hp[0], v1 = hp[1];
        if (j + 1 < end) {
            sN = g_col[j + 1];
            eN = g_esp[sN] + g_esp[NN + sN];
        }
        float e = es + edst;
        e = e > 0.f ? e : 0.2f * e;
        float p = __expf(e);
        sum += p;
        acc[0] += p * v0.x; acc[1] += p * v0.y;
        acc[2] += p * v0.z; acc[3] += p * v0.w;
        acc[4] += p * v1.x; acc[5] += p * v1.y;
        acc[6] += p * v1.z; acc[7] += p * v1.w;
    }

    float inv = 1.f / (sum + 1e-16f);
    int c = lane * 8;
    #pragma unroll
    for (int q = 0; q < 8; q++) {
        float v = acc[q] * inv + bias[c + q];
        v = fmaxf(v, 0.f);
        out[(size_t)w * 512 + (FIRST ? 0 : 256) + c + q] = v;
        if (FIRST) {
            __nv_bfloat16 h = __float2bfloat16(v);
            g_ahi[(size_t)w * CC + c + q] = h;
            g_alo[(size_t)w * CC + c + q] = __float2bfloat16(v - __bfloat162float(h));
        }
    }
}

// ---------------- launch ----------------
extern "C" void kernel_launch(void* const* d_in, const int* in_sizes, int n_in,
                              void* d_out, int out_size) {
    const float* x    = (const float*)d_in[0];
    const int*   ei   = (const int*)d_in[1];
    const float* W1   = (const float*)d_in[2];
    const float* a1s  = (const float*)d_in[3];
    const float* a1d  = (const float*)d_in[4];
    const float* b1   = (const float*)d_in[5];
    const float* W2   = (const float*)d_in[6];
    const float* a2s  = (const float*)d_in[7];
    const float* a2d  = (const float*)d_in[8];
    const float* b2   = (const float*)d_in[9];
    float* out = (float*)d_out;

    prep_kernel<<<(NN * DD + 255) / 256, 256>>>(x, W1, W2);
    count_deg_kernel<<<(ETOT + 255) / 256, 256>>>(ei);
    scan_kernel<<<1, 1024>>>();
    fill_kernel<<<(ETOT + 255) / 256, 256>>>(ei);

    dim3 ggrid((NN + 127) / 128, 2);
    int wnode_blocks = (NN + 7) / 8;

    mma_gemm_kernel<128, 1><<<ggrid, 256>>>(a1s, a1d);
    aggregate_kernel<true><<<wnode_blocks, 256>>>(b1, out);

    mma_gemm_kernel<256, 2><<<ggrid, 256>>>(a2s, a2d);
    aggregate_kernel<false><<<wnode_blocks, 256>>>(b2, out);
}

// round 5
// speedup vs baseline: 1.8634x; 1.8634x over previous
#include <cuda_runtime.h>
#include <cuda_bf16.h>
#include <cstdint>
#include <math.h>

#define NN 50000
#define EE 500000
#define ETOT (EE + NN)
#define CC 256
#define DD 128
#define NB_SCAN 49   // ceil(50000/1024)

// ---------------- scratch (static __device__, no allocation) ----------------
__device__ float g_h[(size_t)NN * CC];           // transformed features (fp32)
__device__ __nv_bfloat16 g_ahi[(size_t)NN * CC]; // split-bf16 A (hi)
__device__ __nv_bfloat16 g_alo[(size_t)NN * CC]; // split-bf16 A (lo)
__device__ __nv_bfloat16 g_w1hi[256 * 128], g_w1lo[256 * 128];
__device__ __nv_bfloat16 g_w2hi[256 * 256], g_w2lo[256 * 256];
__device__ float g_esrc[NN];
__device__ float g_edst[NN];
__device__ int   g_deg[NN];
__device__ int   g_rowptr[NN + 1];
__device__ int   g_cursor[NN];
__device__ int   g_col[ETOT];
__device__ int   g_bsum[NB_SCAN];

// ---------------- helpers ----------------
__device__ __forceinline__ uint32_t smem_u32(const void* p) {
    uint32_t a;
    asm("{ .reg .u64 t; cvta.to.shared.u64 t, %1; cvt.u32.u64 %0, t; }"
        : "=r"(a) : "l"(p));
    return a;
}

#define LDSM4(R, addr) \
    asm volatile("ldmatrix.sync.aligned.m8n8.x4.shared.b16 {%0,%1,%2,%3}, [%4];" \
                 : "=r"((R)[0]), "=r"((R)[1]), "=r"((R)[2]), "=r"((R)[3]) \
                 : "r"(addr))

#define MMA_BF16(d, a, b0, b1) \
    asm volatile("mma.sync.aligned.m16n8k16.row.col.f32.bf16.bf16.f32 " \
                 "{%0,%1,%2,%3},{%4,%5,%6,%7},{%8,%9},{%0,%1,%2,%3};" \
                 : "+f"((d)[0]), "+f"((d)[1]), "+f"((d)[2]), "+f"((d)[3]) \
                 : "r"((a)[0]), "r"((a)[1]), "r"((a)[2]), "r"((a)[3]), \
                   "r"(b0), "r"(b1))

// ---------------- prep: split-bf16 conversions (fused) ----------------
__global__ void prep_kernel(const float* __restrict__ x,
                            const float* __restrict__ W1,
                            const float* __restrict__ W2) {
    int i = blockIdx.x * blockDim.x + threadIdx.x;
    if (i < NN * DD) {
        float v = x[i];
        __nv_bfloat16 h = __float2bfloat16(v);
        g_ahi[i] = h;
        g_alo[i] = __float2bfloat16(v - __bfloat162float(h));
    }
    if (i < 256 * 128) {
        float v = W1[i];
        __nv_bfloat16 h = __float2bfloat16(v);
        g_w1hi[i] = h;
        g_w1lo[i] = __float2bfloat16(v - __bfloat162float(h));
    }
    if (i < 256 * 256) {
        float v = W2[i];
        __nv_bfloat16 h = __float2bfloat16(v);
        g_w2hi[i] = h;
        g_w2lo[i] = __float2bfloat16(v - __bfloat162float(h));
    }
}

// ---------------- CSR build (R3-proven multi-block version) ----------------
__global__ void zero_deg_kernel() {
    int i = blockIdx.x * blockDim.x + threadIdx.x;
    if (i < NN) g_deg[i] = 0;
}

__global__ void count_deg_kernel(const int* __restrict__ ei) {
    int i = blockIdx.x * blockDim.x + threadIdx.x;
    if (i >= ETOT) return;
    int d = (i < EE) ? ei[EE + i] : (i - EE);
    atomicAdd(&g_deg[d], 1);
}

__global__ void scan1_kernel() {
    __shared__ int sh[1024];
    int t = threadIdx.x;
    int i = blockIdx.x * 1024 + t;
    int v = (i < NN) ? g_deg[i] : 0;
    sh[t] = v;
    __syncthreads();
    #pragma unroll
    for (int off = 1; off < 1024; off <<= 1) {
        int x = (t >= off) ? sh[t - off] : 0;
        __syncthreads();
        sh[t] += x;
        __syncthreads();
    }
    if (i < NN) g_rowptr[i + 1] = sh[t];
    if (t == 1023) g_bsum[blockIdx.x] = sh[1023];
}

__global__ void scan2_kernel() {
    __shared__ int sh[64];
    int t = threadIdx.x;
    int v = (t < NB_SCAN) ? g_bsum[t] : 0;
    sh[t] = v;
    __syncthreads();
    #pragma unroll
    for (int o = 1; o < 64; o <<= 1) {
        int x = (t >= o) ? sh[t - o] : 0;
        __syncthreads();
        sh[t] += x;
        __syncthreads();
    }
    if (t < NB_SCAN) g_bsum[t] = sh[t] - v;   // exclusive
}

__global__ void scan3_kernel() {
    int t = threadIdx.x;
    int i = blockIdx.x * 1024 + t;
    if (i < NN) {
        int r = g_rowptr[i + 1] + g_bsum[blockIdx.x];
        g_rowptr[i + 1] = r;
        if (i + 1 < NN) g_cursor[i + 1] = r;
        if (i == 0) { g_rowptr[0] = 0; g_cursor[0] = 0; }
    }
}

__global__ void fill_kernel(const int* __restrict__ ei) {
    int i = blockIdx.x * blockDim.x + threadIdx.x;
    if (i >= ETOT) return;
    int s, d;
    if (i < EE) { s = ei[i]; d = ei[EE + i]; }
    else        { s = i - EE; d = s; }
    int pos = atomicAdd(&g_cursor[d], 1);
    g_col[pos] = s;
}

// ---------------- HMMA GEMM: g_h[M,256] = A[M,K] * W[256,K]^T ----------------
// BM=128, BN=128, BK=32; 8 warps (2 m x 4 n), warp tile 64x32 via m16n8k16.
// Split-bf16: acc += Ahi*Whi + Ahi*Wlo + Alo*Whi (fp32 accum).
#define SST 40   // smem row stride in bf16 elems (conflict-free for ldmatrix)

template <int K, int LAYER>
__global__ __launch_bounds__(256) void mma_gemm_kernel() {
    __shared__ __align__(16) __nv_bfloat16 sA[2][128 * SST];
    __shared__ __align__(16) __nv_bfloat16 sB[2][128 * SST];

    const __nv_bfloat16* __restrict__ Ahi = g_ahi;
    const __nv_bfloat16* __restrict__ Alo = g_alo;
    const __nv_bfloat16* __restrict__ Whi = (LAYER == 1) ? g_w1hi : g_w2hi;
    const __nv_bfloat16* __restrict__ Wlo = (LAYER == 1) ? g_w1lo : g_w2lo;

    int tid = threadIdx.x;
    int wid = tid >> 5;
    int lane = tid & 31;
    int bm = blockIdx.x * 128;
    int bn = blockIdx.y * 128;
    int wm = (wid & 1) * 64;
    int wn = (wid >> 1) * 32;

    float acc[4][4][4];
    #pragma unroll
    for (int a = 0; a < 4; a++)
        #pragma unroll
        for (int b = 0; b < 4; b++)
            #pragma unroll
            for (int c = 0; c < 4; c++) acc[a][b][c] = 0.f;

    uint32_t aHb = smem_u32(&sA[0][0]);
    uint32_t aLb = smem_u32(&sA[1][0]);
    uint32_t bHb = smem_u32(&sB[0][0]);
    uint32_t bLb = smem_u32(&sB[1][0]);

    int a_row = wm + (lane & 15);
    int a_k8  = (lane >> 4) << 3;
    int b_row = wn + (lane & 7) + ((lane >> 4) << 3);
    int b_k8  = ((lane >> 3) & 1) << 3;

    for (int k0 = 0; k0 < K; k0 += 32) {
        #pragma unroll
        for (int it = 0; it < 2; it++) {
            int idx = tid + it * 256;          // 0..511
            int r = idx >> 2;
            int q = (idx & 3) << 3;
            int row = bm + r;
            uint4 vh = make_uint4(0u, 0u, 0u, 0u);
            uint4 vl = make_uint4(0u, 0u, 0u, 0u);
            if (row < NN) {
                vh = *(const uint4*)&Ahi[(size_t)row * K + k0 + q];
                vl = *(const uint4*)&Alo[(size_t)row * K + k0 + q];
            }
            *(uint4*)&sA[0][r * SST + q] = vh;
            *(uint4*)&sA[1][r * SST + q] = vl;
            *(uint4*)&sB[0][r * SST + q] = *(const uint4*)&Whi[(size_t)(bn + r) * K + k0 + q];
            *(uint4*)&sB[1][r * SST + q] = *(const uint4*)&Wlo[(size_t)(bn + r) * K + k0 + q];
        }
        __syncthreads();

        #pragma unroll
        for (int ks = 0; ks < 2; ks++) {
            int kk = ks * 16;
            uint32_t aH[4][4], aL[4][4], bH[2][4], bL[2][4];
            #pragma unroll
            for (int mt = 0; mt < 4; mt++) {
                uint32_t off = (uint32_t)(((a_row + mt * 16) * SST + kk + a_k8) * 2);
                LDSM4(aH[mt], aHb + off);
                LDSM4(aL[mt], aLb + off);
            }
            #pragma unroll
            for (int bt = 0; bt < 2; bt++) {
                uint32_t off = (uint32_t)(((b_row + bt * 16) * SST + kk + b_k8) * 2);
                LDSM4(bH[bt], bHb + off);
                LDSM4(bL[bt], bLb + off);
            }
            #pragma unroll
            for (int mt = 0; mt < 4; mt++) {
                #pragma unroll
                for (int nt = 0; nt < 4; nt++) {
                    int bt = nt >> 1;
                    int sb = (nt & 1) * 2;
                    MMA_BF16(acc[mt][nt], aH[mt], bH[bt][sb], bH[bt][sb + 1]);
                    MMA_BF16(acc[mt][nt], aH[mt], bL[bt][sb], bL[bt][sb + 1]);
                    MMA_BF16(acc[mt][nt], aL[mt], bH[bt][sb], bH[bt][sb + 1]);
                }
            }
        }
        __syncthreads();
    }

    // ---- epilogue: regs -> g_h (fp32) ----
    int gid = lane >> 2;
    int tig = lane & 3;
    #pragma unroll
    for (int mt = 0; mt < 4; mt++) {
        #pragma unroll
        for (int nt = 0; nt < 4; nt++) {
            int row0 = bm + wm + mt * 16 + gid;
            int col = bn + wn + nt * 8 + tig * 2;
            if (row0 < NN)
                *(float2*)&g_h[(size_t)row0 * CC + col] =
                    make_float2(acc[mt][nt][0], acc[mt][nt][1]);
            int row1 = row0 + 8;
            if (row1 < NN)
                *(float2*)&g_h[(size_t)row1 * CC + col] =
                    make_float2(acc[mt][nt][2], acc[mt][nt][3]);
        }
    }
}

// ---------------- per-node attention dots: warp per node ----------------
__global__ void dots_kernel(const float* __restrict__ asrc,
                            const float* __restrict__ adst) {
    int w = (blockIdx.x * blockDim.x + threadIdx.x) >> 5;
    int lane = threadIdx.x & 31;
    if (w >= NN) return;
    const float4* hp = (const float4*)(g_h + (size_t)w * CC);
    float4 v0 = hp[lane * 2], v1 = hp[lane * 2 + 1];
    const float4* s4 = (const float4*)asrc;
    const float4* d4 = (const float4*)adst;
    float4 s0 = s4[lane * 2], s1 = s4[lane * 2 + 1];
    float4 q0 = d4[lane * 2], q1 = d4[lane * 2 + 1];
    float es = v0.x * s0.x + v0.y * s0.y + v0.z * s0.z + v0.w * s0.w
             + v1.x * s1.x + v1.y * s1.y + v1.z * s1.z + v1.w * s1.w;
    float ed = v0.x * q0.x + v0.y * q0.y + v0.z * q0.z + v0.w * q0.w
             + v1.x * q1.x + v1.y * q1.y + v1.z * q1.z + v1.w * q1.w;
    #pragma unroll
    for (int o = 16; o; o >>= 1) {
        es += __shfl_xor_sync(0xFFFFFFFFu, es, o);
        ed += __shfl_xor_sync(0xFFFFFFFFu, ed, o);
    }
    if (lane == 0) { g_esrc[w] = es; g_edst[w] = ed; }
}

// ---------------- softmax + aggregate: warp per destination node ----------------
// Single pass (e bounded, softmax shift-invariant); index/e prefetch.
template <bool FIRST>
__global__ void aggregate_kernel(const float* __restrict__ bias,
                                 float* __restrict__ out) {
    int w = (blockIdx.x * blockDim.x + threadIdx.x) >> 5;
    if (w >= NN) return;
    int lane = threadIdx.x & 31;

    float edst = g_edst[w];
    int beg = g_rowptr[w];
    int end = g_rowptr[w + 1];

    float sum = 0.f;
    float acc[8] = {0.f, 0.f, 0.f, 0.f, 0.f, 0.f, 0.f, 0.f};

    int sN = g_col[beg];                      // deg >= 1 (self-loop)
    float eN = g_esrc[sN];

    for (int j = beg; j < end; j++) {
        int s = sN;
        float es = eN;
        const float4* hp = (const float4*)(g_h + (size_t)s * CC + lane * 8);
        float4 v0 = hp[0], v1 = hp[1];
        if (j + 1 < end) {
            sN = g_col[j + 1];
            eN = g_esrc[sN];
        }
        float e = es + edst;
        e = e > 0.f ? e : 0.2f * e;
        float p = __expf(e);
        sum += p;
        acc[0] += p * v0.x; acc[1] += p * v0.y;
        acc[2] += p * v0.z; acc[3] += p * v0.w;
        acc[4] += p * v1.x; acc[5] += p * v1.y;
        acc[6] += p * v1.z; acc[7] += p * v1.w;
    }

    float inv = 1.f / (sum + 1e-16f);
    int c = lane * 8;
    #pragma unroll
    for (int q = 0; q < 8; q++) {
        float v = acc[q] * inv + bias[c + q];
        v = fmaxf(v, 0.f);
        out[(size_t)w * 512 + (FIRST ? 0 : 256) + c + q] = v;
        if (FIRST) {
            __nv_bfloat16 h = __float2bfloat16(v);
            g_ahi[(size_t)w * CC + c + q] = h;
            g_alo[(size_t)w * CC + c + q] = __float2bfloat16(v - __bfloat162float(h));
        }
    }
}

// ---------------- launch ----------------
extern "C" void kernel_launch(void* const* d_in, const int* in_sizes, int n_in,
                              void* d_out, int out_size) {
    const float* x    = (const float*)d_in[0];
    const int*   ei   = (const int*)d_in[1];
    const float* W1   = (const float*)d_in[2];
    const float* a1s  = (const float*)d_in[3];
    const float* a1d  = (const float*)d_in[4];
    const float* b1   = (const float*)d_in[5];
    const float* W2   = (const float*)d_in[6];
    const float* a2s  = (const float*)d_in[7];
    const float* a2d  = (const float*)d_in[8];
    const float* b2   = (const float*)d_in[9];
    float* out = (float*)d_out;

    // one-time resources (no device memory)
    static cudaStream_t sB = nullptr;
    static cudaEvent_t evFork = nullptr, evJoin = nullptr;
    if (!sB) {
        cudaStreamCreateWithFlags(&sB, cudaStreamNonBlocking);
        cudaEventCreateWithFlags(&evFork, cudaEventDisableTiming);
        cudaEventCreateWithFlags(&evJoin, cudaEventDisableTiming);
    }
    cudaStream_t s0 = (cudaStream_t)0;

    // ---- fork: CSR build on sB, concurrent with prep/GEMM1/dots1 ----
    cudaEventRecord(evFork, s0);
    cudaStreamWaitEvent(sB, evFork, 0);

    zero_deg_kernel<<<(NN + 255) / 256, 256, 0, sB>>>();
    count_deg_kernel<<<(ETOT + 255) / 256, 256, 0, sB>>>(ei);
    scan1_kernel<<<NB_SCAN, 1024, 0, sB>>>();
    scan2_kernel<<<1, 64, 0, sB>>>();
    scan3_kernel<<<NB_SCAN, 1024, 0, sB>>>();
    fill_kernel<<<(ETOT + 255) / 256, 256, 0, sB>>>(ei);
    cudaEventRecord(evJoin, sB);

    dim3 ggrid((NN + 127) / 128, 2);
    int wnode_blocks = (NN + 7) / 8;

    // ---- main stream: prep + layer-1 GEMM/dots ----
    prep_kernel<<<(NN * DD + 255) / 256, 256, 0, s0>>>(x, W1, W2);
    mma_gemm_kernel<128, 1><<<ggrid, 256, 0, s0>>>();
    dots_kernel<<<wnode_blocks, 256, 0, s0>>>(a1s, a1d);

    // ---- join: aggregate needs CSR ----
    cudaStreamWaitEvent(s0, evJoin, 0);
    aggregate_kernel<true><<<wnode_blocks, 256, 0, s0>>>(b1, out);

    // ---- layer 2 ----
    mma_gemm_kernel<256, 2><<<ggrid, 256, 0, s0>>>();
    dots_kernel<<<wnode_blocks, 256, 0, s0>>>(a2s, a2d);
    aggregate_kernel<false><<<wnode_blocks, 256, 0, s0>>>(b2, out);
}

// round 6
// speedup vs baseline: 2.0432x; 1.0965x over previous
#include <cuda_runtime.h>
#include <cuda_bf16.h>
#include <cuda_fp16.h>
#include <cstdint>
#include <math.h>

#define NN 50000
#define EE 500000
#define ETOT (EE + NN)
#define CC 256
#define DD 128
#define NB_SCAN 49   // ceil(50000/1024)

// ---------------- scratch (static __device__, no allocation) ----------------
__device__ __half g_hf16[(size_t)NN * CC];       // transformed features (fp16)
__device__ __nv_bfloat16 g_ahi[(size_t)NN * CC]; // split-bf16 A (hi)
__device__ __nv_bfloat16 g_alo[(size_t)NN * CC]; // split-bf16 A (lo)
__device__ __nv_bfloat16 g_w1hi[256 * 128], g_w1lo[256 * 128];
__device__ __nv_bfloat16 g_w2hi[256 * 256], g_w2lo[256 * 256];
__device__ float g_esrc[NN];
__device__ float g_edst[NN];
__device__ int   g_deg[NN];
__device__ int   g_rowptr[NN + 1];
__device__ int   g_cursor[NN];
__device__ int   g_col[ETOT];
__device__ int   g_bsum[NB_SCAN];

// ---------------- helpers ----------------
__device__ __forceinline__ uint32_t smem_u32(const void* p) {
    uint32_t a;
    asm("{ .reg .u64 t; cvta.to.shared.u64 t, %1; cvt.u32.u64 %0, t; }"
        : "=r"(a) : "l"(p));
    return a;
}

#define LDSM4(R, addr) \
    asm volatile("ldmatrix.sync.aligned.m8n8.x4.shared.b16 {%0,%1,%2,%3}, [%4];" \
                 : "=r"((R)[0]), "=r"((R)[1]), "=r"((R)[2]), "=r"((R)[3]) \
                 : "r"(addr))

#define MMA_BF16(d, a, b0, b1) \
    asm volatile("mma.sync.aligned.m16n8k16.row.col.f32.bf16.bf16.f32 " \
                 "{%0,%1,%2,%3},{%4,%5,%6,%7},{%8,%9},{%0,%1,%2,%3};" \
                 : "+f"((d)[0]), "+f"((d)[1]), "+f"((d)[2]), "+f"((d)[3]) \
                 : "r"((a)[0]), "r"((a)[1]), "r"((a)[2]), "r"((a)[3]), \
                   "r"(b0), "r"(b1))

// ---------------- prep: split-bf16 conversions (fused) ----------------
__global__ void prep_kernel(const float* __restrict__ x,
                            const float* __restrict__ W1,
                            const float* __restrict__ W2) {
    int i = blockIdx.x * blockDim.x + threadIdx.x;
    if (i < NN * DD) {
        float v = x[i];
        __nv_bfloat16 h = __float2bfloat16(v);
        g_ahi[i] = h;
        g_alo[i] = __float2bfloat16(v - __bfloat162float(h));
    }
    if (i < 256 * 128) {
        float v = W1[i];
        __nv_bfloat16 h = __float2bfloat16(v);
        g_w1hi[i] = h;
        g_w1lo[i] = __float2bfloat16(v - __bfloat162float(h));
    }
    if (i < 256 * 256) {
        float v = W2[i];
        __nv_bfloat16 h = __float2bfloat16(v);
        g_w2hi[i] = h;
        g_w2lo[i] = __float2bfloat16(v - __bfloat162float(h));
    }
}

// ---------------- CSR build ----------------
__global__ void zero_deg_kernel() {
    int i = blockIdx.x * blockDim.x + threadIdx.x;
    if (i < NN) g_deg[i] = 0;
}

__global__ void count_deg_kernel(const int* __restrict__ ei) {
    int i = blockIdx.x * blockDim.x + threadIdx.x;
    if (i >= ETOT) return;
    int d = (i < EE) ? ei[EE + i] : (i - EE);
    atomicAdd(&g_deg[d], 1);
}

__global__ void scan1_kernel() {
    __shared__ int sh[1024];
    int t = threadIdx.x;
    int i = blockIdx.x * 1024 + t;
    int v = (i < NN) ? g_deg[i] : 0;
    sh[t] = v;
    __syncthreads();
    #pragma unroll
    for (int off = 1; off < 1024; off <<= 1) {
        int x = (t >= off) ? sh[t - off] : 0;
        __syncthreads();
        sh[t] += x;
        __syncthreads();
    }
    if (i < NN) g_rowptr[i + 1] = sh[t];
    if (t == 1023) g_bsum[blockIdx.x] = sh[1023];
}

__global__ void scan2_kernel() {
    __shared__ int sh[64];
    int t = threadIdx.x;
    int v = (t < NB_SCAN) ? g_bsum[t] : 0;
    sh[t] = v;
    __syncthreads();
    #pragma unroll
    for (int o = 1; o < 64; o <<= 1) {
        int x = (t >= o) ? sh[t - o] : 0;
        __syncthreads();
        sh[t] += x;
        __syncthreads();
    }
    if (t < NB_SCAN) g_bsum[t] = sh[t] - v;   // exclusive
}

__global__ void scan3_kernel() {
    int t = threadIdx.x;
    int i = blockIdx.x * 1024 + t;
    if (i < NN) {
        int r = g_rowptr[i + 1] + g_bsum[blockIdx.x];
        g_rowptr[i + 1] = r;
        if (i + 1 < NN) g_cursor[i + 1] = r;
        if (i == 0) { g_rowptr[0] = 0; g_cursor[0] = 0; }
    }
}

__global__ void fill_kernel(const int* __restrict__ ei) {
    int i = blockIdx.x * blockDim.x + threadIdx.x;
    if (i >= ETOT) return;
    int s, d;
    if (i < EE) { s = ei[i]; d = ei[EE + i]; }
    else        { s = i - EE; d = s; }
    int pos = atomicAdd(&g_cursor[d], 1);
    g_col[pos] = s;
}

// ---------------- HMMA GEMM: g_hf16[M,256] = A[M,K] * W[256,K]^T ----------------
// BM=128, BN=128, BK=32; 8 warps (2m x 4n), warp tile 64x32 via m16n8k16.
// Split-bf16 inputs: acc += Ahi*Whi + Ahi*Wlo + Alo*Whi (fp32 accum); fp16 output.
#define SST 40   // smem row stride in bf16 elems (conflict-free for ldmatrix)

template <int K, int LAYER>
__global__ __launch_bounds__(256) void mma_gemm_kernel() {
    __shared__ __align__(16) __nv_bfloat16 sA[2][128 * SST];
    __shared__ __align__(16) __nv_bfloat16 sB[2][128 * SST];

    const __nv_bfloat16* __restrict__ Ahi = g_ahi;
    const __nv_bfloat16* __restrict__ Alo = g_alo;
    const __nv_bfloat16* __restrict__ Whi = (LAYER == 1) ? g_w1hi : g_w2hi;
    const __nv_bfloat16* __restrict__ Wlo = (LAYER == 1) ? g_w1lo : g_w2lo;

    int tid = threadIdx.x;
    int wid = tid >> 5;
    int lane = tid & 31;
    int bm = blockIdx.x * 128;
    int bn = blockIdx.y * 128;
    int wm = (wid & 1) * 64;
    int wn = (wid >> 1) * 32;

    float acc[4][4][4];
    #pragma unroll
    for (int a = 0; a < 4; a++)
        #pragma unroll
        for (int b = 0; b < 4; b++)
            #pragma unroll
            for (int c = 0; c < 4; c++) acc[a][b][c] = 0.f;

    uint32_t aHb = smem_u32(&sA[0][0]);
    uint32_t aLb = smem_u32(&sA[1][0]);
    uint32_t bHb = smem_u32(&sB[0][0]);
    uint32_t bLb = smem_u32(&sB[1][0]);

    int a_row = wm + (lane & 15);
    int a_k8  = (lane >> 4) << 3;
    int b_row = wn + (lane & 7) + ((lane >> 4) << 3);
    int b_k8  = ((lane >> 3) & 1) << 3;

    for (int k0 = 0; k0 < K; k0 += 32) {
        #pragma unroll
        for (int it = 0; it < 2; it++) {
            int idx = tid + it * 256;          // 0..511
            int r = idx >> 2;
            int q = (idx & 3) << 3;
            int row = bm + r;
            uint4 vh = make_uint4(0u, 0u, 0u, 0u);
            uint4 vl = make_uint4(0u, 0u, 0u, 0u);
            if (row < NN) {
                vh = *(const uint4*)&Ahi[(size_t)row * K + k0 + q];
                vl = *(const uint4*)&Alo[(size_t)row * K + k0 + q];
            }
            *(uint4*)&sA[0][r * SST + q] = vh;
            *(uint4*)&sA[1][r * SST + q] = vl;
            *(uint4*)&sB[0][r * SST + q] = *(const uint4*)&Whi[(size_t)(bn + r) * K + k0 + q];
            *(uint4*)&sB[1][r * SST + q] = *(const uint4*)&Wlo[(size_t)(bn + r) * K + k0 + q];
        }
        __syncthreads();

        #pragma unroll
        for (int ks = 0; ks < 2; ks++) {
            int kk = ks * 16;
            uint32_t aH[4][4], aL[4][4], bH[2][4], bL[2][4];
            #pragma unroll
            for (int mt = 0; mt < 4; mt++) {
                uint32_t off = (uint32_t)(((a_row + mt * 16) * SST + kk + a_k8) * 2);
                LDSM4(aH[mt], aHb + off);
                LDSM4(aL[mt], aLb + off);
            }
            #pragma unroll
            for (int bt = 0; bt < 2; bt++) {
                uint32_t off = (uint32_t)(((b_row + bt * 16) * SST + kk + b_k8) * 2);
                LDSM4(bH[bt], bHb + off);
                LDSM4(bL[bt], bLb + off);
            }
            #pragma unroll
            for (int mt = 0; mt < 4; mt++) {
                #pragma unroll
                for (int nt = 0; nt < 4; nt++) {
                    int bt = nt >> 1;
                    int sb = (nt & 1) * 2;
                    MMA_BF16(acc[mt][nt], aH[mt], bH[bt][sb], bH[bt][sb + 1]);
                    MMA_BF16(acc[mt][nt], aH[mt], bL[bt][sb], bL[bt][sb + 1]);
                    MMA_BF16(acc[mt][nt], aL[mt], bH[bt][sb], bH[bt][sb + 1]);
                }
            }
        }
        __syncthreads();
    }

    // ---- epilogue: regs -> g_hf16 ----
    int gid = lane >> 2;
    int tig = lane & 3;
    #pragma unroll
    for (int mt = 0; mt < 4; mt++) {
        #pragma unroll
        for (int nt = 0; nt < 4; nt++) {
            int row0 = bm + wm + mt * 16 + gid;
            int col = bn + wn + nt * 8 + tig * 2;
            if (row0 < NN)
                *(__half2*)&g_hf16[(size_t)row0 * CC + col] =
                    __floats2half2_rn(acc[mt][nt][0], acc[mt][nt][1]);
            int row1 = row0 + 8;
            if (row1 < NN)
                *(__half2*)&g_hf16[(size_t)row1 * CC + col] =
                    __floats2half2_rn(acc[mt][nt][2], acc[mt][nt][3]);
        }
    }
}

// ---------------- per-node attention dots: warp per node (fp16 h) ----------------
__global__ void dots_kernel(const float* __restrict__ asrc,
                            const float* __restrict__ adst) {
    int w = (blockIdx.x * blockDim.x + threadIdx.x) >> 5;
    int lane = threadIdx.x & 31;
    if (w >= NN) return;
    uint4 u = *(const uint4*)&g_hf16[(size_t)w * CC + lane * 8];
    float2 f0 = __half22float2(*(__half2*)&u.x);
    float2 f1 = __half22float2(*(__half2*)&u.y);
    float2 f2 = __half22float2(*(__half2*)&u.z);
    float2 f3 = __half22float2(*(__half2*)&u.w);
    const float4* s4 = (const float4*)asrc;
    const float4* d4 = (const float4*)adst;
    float4 s0 = s4[lane * 2], s1 = s4[lane * 2 + 1];
    float4 q0 = d4[lane * 2], q1 = d4[lane * 2 + 1];
    float es = f0.x * s0.x + f0.y * s0.y + f1.x * s0.z + f1.y * s0.w
             + f2.x * s1.x + f2.y * s1.y + f3.x * s1.z + f3.y * s1.w;
    float ed = f0.x * q0.x + f0.y * q0.y + f1.x * q0.z + f1.y * q0.w
             + f2.x * q1.x + f2.y * q1.y + f3.x * q1.z + f3.y * q1.w;
    #pragma unroll
    for (int o = 16; o; o >>= 1) {
        es += __shfl_xor_sync(0xFFFFFFFFu, es, o);
        ed += __shfl_xor_sync(0xFFFFFFFFu, ed, o);
    }
    if (lane == 0) { g_esrc[w] = es; g_edst[w] = ed; }
}

// ---------------- softmax + aggregate: warp per destination node ----------------
// Single pass (e bounded, softmax shift-invariant); fp16 gather; index prefetch.
template <bool FIRST>
__global__ void aggregate_kernel(const float* __restrict__ bias,
                                 float* __restrict__ out) {
    int w = (blockIdx.x * blockDim.x + threadIdx.x) >> 5;
    if (w >= NN) return;
    int lane = threadIdx.x & 31;

    float edst = g_edst[w];
    int beg = g_rowptr[w];
    int end = g_rowptr[w + 1];

    float sum = 0.f;
    float acc[8] = {0.f, 0.f, 0.f, 0.f, 0.f, 0.f, 0.f, 0.f};

    int sN = g_col[beg];                      // deg >= 1 (self-loop)
    float eN = g_esrc[sN];

    for (int j = beg; j < end; j++) {
        int s = sN;
        float es = eN;
        uint4 u = *(const uint4*)&g_hf16[(size_t)s * CC + lane * 8];
        if (j + 1 < end) {
            sN = g_col[j + 1];
            eN = g_esrc[sN];
        }
        float e = es + edst;
        e = e > 0.f ? e : 0.2f * e;
        float p = __expf(e);
        sum += p;
        float2 f0 = __half22float2(*(__half2*)&u.x);
        float2 f1 = __half22float2(*(__half2*)&u.y);
        float2 f2 = __half22float2(*(__half2*)&u.z);
        float2 f3 = __half22float2(*(__half2*)&u.w);
        acc[0] += p * f0.x; acc[1] += p * f0.y;
        acc[2] += p * f1.x; acc[3] += p * f1.y;
        acc[4] += p * f2.x; acc[5] += p * f2.y;
        acc[6] += p * f3.x; acc[7] += p * f3.y;
    }

    float inv = 1.f / (sum + 1e-16f);
    int c = lane * 8;
    #pragma unroll
    for (int q = 0; q < 8; q++) {
        float v = acc[q] * inv + bias[c + q];
        v = fmaxf(v, 0.f);
        out[(size_t)w * 512 + (FIRST ? 0 : 256) + c + q] = v;
        if (FIRST) {
            __nv_bfloat16 h = __float2bfloat16(v);
            g_ahi[(size_t)w * CC + c + q] = h;
            g_alo[(size_t)w * CC + c + q] = __float2bfloat16(v - __bfloat162float(h));
        }
    }
}

// ---------------- launch ----------------
extern "C" void kernel_launch(void* const* d_in, const int* in_sizes, int n_in,
                              void* d_out, int out_size) {
    const float* x    = (const float*)d_in[0];
    const int*   ei   = (const int*)d_in[1];
    const float* W1   = (const float*)d_in[2];
    const float* a1s  = (const float*)d_in[3];
    const float* a1d  = (const float*)d_in[4];
    const float* b1   = (const float*)d_in[5];
    const float* W2   = (const float*)d_in[6];
    const float* a2s  = (const float*)d_in[7];
    const float* a2d  = (const float*)d_in[8];
    const float* b2   = (const float*)d_in[9];
    float* out = (float*)d_out;

    static cudaStream_t sB = nullptr;
    static cudaEvent_t evFork = nullptr, evJoin = nullptr;
    if (!sB) {
        cudaStreamCreateWithFlags(&sB, cudaStreamNonBlocking);
        cudaEventCreateWithFlags(&evFork, cudaEventDisableTiming);
        cudaEventCreateWithFlags(&evJoin, cudaEventDisableTiming);
    }
    cudaStream_t s0 = (cudaStream_t)0;

    // ---- fork: CSR build on sB, concurrent with prep/GEMM1/dots1 ----
    cudaEventRecord(evFork, s0);
    cudaStreamWaitEvent(sB, evFork, 0);

    zero_deg_kernel<<<(NN + 255) / 256, 256, 0, sB>>>();
    count_deg_kernel<<<(ETOT + 255) / 256, 256, 0, sB>>>(ei);
    scan1_kernel<<<NB_SCAN, 1024, 0, sB>>>();
    scan2_kernel<<<1, 64, 0, sB>>>();
    scan3_kernel<<<NB_SCAN, 1024, 0, sB>>>();
    fill_kernel<<<(ETOT + 255) / 256, 256, 0, sB>>>(ei);
    cudaEventRecord(evJoin, sB);

    dim3 ggrid((NN + 127) / 128, 2);
    int wnode_blocks = (NN + 7) / 8;

    // ---- main stream: prep + layer-1 GEMM/dots ----
    prep_kernel<<<(NN * DD + 255) / 256, 256, 0, s0>>>(x, W1, W2);
    mma_gemm_kernel<128, 1><<<ggrid, 256, 0, s0>>>();
    dots_kernel<<<wnode_blocks, 256, 0, s0>>>(a1s, a1d);

    // ---- join: aggregate needs CSR ----
    cudaStreamWaitEvent(s0, evJoin, 0);
    aggregate_kernel<true><<<wnode_blocks, 256, 0, s0>>>(b1, out);

    // ---- layer 2 ----
    mma_gemm_kernel<256, 2><<<ggrid, 256, 0, s0>>>();
    dots_kernel<<<wnode_blocks, 256, 0, s0>>>(a2s, a2d);
    aggregate_kernel<false><<<wnode_blocks, 256, 0, s0>>>(b2, out);
}

// round 7
// speedup vs baseline: 2.0837x; 1.0198x over previous
#include <cuda_runtime.h>
#include <cuda_bf16.h>
#include <cuda_fp16.h>
#include <cstdint>
#include <math.h>

#define NN 50000
#define EE 500000
#define ETOT (EE + NN)
#define CC 256
#define DD 128
#define NB_SCAN 49   // ceil(50000/1024)

// ---------------- scratch (static __device__, no allocation) ----------------
__device__ __half g_hf16[(size_t)NN * CC];       // transformed features (fp16)
__device__ __nv_bfloat16 g_ahi[(size_t)NN * CC]; // split-bf16 A (hi)
__device__ __nv_bfloat16 g_alo[(size_t)NN * CC]; // split-bf16 A (lo)
__device__ __nv_bfloat16 g_w1hi[256 * 128], g_w1lo[256 * 128];
__device__ __nv_bfloat16 g_w2hi[256 * 256], g_w2lo[256 * 256];
__device__ float g_esp[2 * NN];   // e_src partials per column-slice
__device__ float g_edp[2 * NN];   // e_dst partials per column-slice
__device__ int   g_deg[NN];
__device__ int   g_rowptr[NN + 1];
__device__ int   g_cursor[NN];
__device__ int   g_col[ETOT];
__device__ int   g_bsum[NB_SCAN];

// ---------------- helpers ----------------
__device__ __forceinline__ uint32_t smem_u32(const void* p) {
    uint32_t a;
    asm("{ .reg .u64 t; cvta.to.shared.u64 t, %1; cvt.u32.u64 %0, t; }"
        : "=r"(a) : "l"(p));
    return a;
}

#define LDSM4(R, addr) \
    asm volatile("ldmatrix.sync.aligned.m8n8.x4.shared.b16 {%0,%1,%2,%3}, [%4];" \
                 : "=r"((R)[0]), "=r"((R)[1]), "=r"((R)[2]), "=r"((R)[3]) \
                 : "r"(addr))

#define MMA_BF16(d, a, b0, b1) \
    asm volatile("mma.sync.aligned.m16n8k16.row.col.f32.bf16.bf16.f32 " \
                 "{%0,%1,%2,%3},{%4,%5,%6,%7},{%8,%9},{%0,%1,%2,%3};" \
                 : "+f"((d)[0]), "+f"((d)[1]), "+f"((d)[2]), "+f"((d)[3]) \
                 : "r"((a)[0]), "r"((a)[1]), "r"((a)[2]), "r"((a)[3]), \
                   "r"(b0), "r"(b1))

// ---------------- prep: split-bf16 conversions (fused) ----------------
__global__ void prep_kernel(const float* __restrict__ x,
                            const float* __restrict__ W1,
                            const float* __restrict__ W2) {
    int i = blockIdx.x * blockDim.x + threadIdx.x;
    if (i < NN * DD) {
        float v = x[i];
        __nv_bfloat16 h = __float2bfloat16(v);
        g_ahi[i] = h;
        g_alo[i] = __float2bfloat16(v - __bfloat162float(h));
    }
    if (i < 256 * 128) {
        float v = W1[i];
        __nv_bfloat16 h = __float2bfloat16(v);
        g_w1hi[i] = h;
        g_w1lo[i] = __float2bfloat16(v - __bfloat162float(h));
    }
    if (i < 256 * 256) {
        float v = W2[i];
        __nv_bfloat16 h = __float2bfloat16(v);
        g_w2hi[i] = h;
        g_w2lo[i] = __float2bfloat16(v - __bfloat162float(h));
    }
}

// ---------------- CSR build ----------------
__global__ void zero_deg_kernel() {
    int i = blockIdx.x * blockDim.x + threadIdx.x;
    if (i < NN) g_deg[i] = 0;
}

__global__ void count_deg_kernel(const int* __restrict__ ei) {
    int i = blockIdx.x * blockDim.x + threadIdx.x;
    if (i >= ETOT) return;
    int d = (i < EE) ? ei[EE + i] : (i - EE);
    atomicAdd(&g_deg[d], 1);
}

__global__ void scan1_kernel() {
    __shared__ int sh[1024];
    int t = threadIdx.x;
    int i = blockIdx.x * 1024 + t;
    int v = (i < NN) ? g_deg[i] : 0;
    sh[t] = v;
    __syncthreads();
    #pragma unroll
    for (int off = 1; off < 1024; off <<= 1) {
        int x = (t >= off) ? sh[t - off] : 0;
        __syncthreads();
        sh[t] += x;
        __syncthreads();
    }
    if (i < NN) g_rowptr[i + 1] = sh[t];
    if (t == 1023) g_bsum[blockIdx.x] = sh[1023];
}

__global__ void scan2_kernel() {
    __shared__ int sh[64];
    int t = threadIdx.x;
    int v = (t < NB_SCAN) ? g_bsum[t] : 0;
    sh[t] = v;
    __syncthreads();
    #pragma unroll
    for (int o = 1; o < 64; o <<= 1) {
        int x = (t >= o) ? sh[t - o] : 0;
        __syncthreads();
        sh[t] += x;
        __syncthreads();
    }
    if (t < NB_SCAN) g_bsum[t] = sh[t] - v;   // exclusive
}

__global__ void scan3_kernel() {
    int t = threadIdx.x;
    int i = blockIdx.x * 1024 + t;
    if (i < NN) {
        int r = g_rowptr[i + 1] + g_bsum[blockIdx.x];
        g_rowptr[i + 1] = r;
        if (i + 1 < NN) g_cursor[i + 1] = r;
        if (i == 0) { g_rowptr[0] = 0; g_cursor[0] = 0; }
    }
}

__global__ void fill_kernel(const int* __restrict__ ei) {
    int i = blockIdx.x * blockDim.x + threadIdx.x;
    if (i >= ETOT) return;
    int s, d;
    if (i < EE) { s = ei[i]; d = ei[EE + i]; }
    else        { s = i - EE; d = s; }
    int pos = atomicAdd(&g_cursor[d], 1);
    g_col[pos] = s;
}

// ---------------- HMMA GEMM + fused dots: g_hf16 = A*W^T, e-partials ----------------
// BM=128, BN=128, BK=32; 8 warps (2m x 4n), warp tile 64x32 via m16n8k16.
// Split-bf16 inputs: acc += Ahi*Whi + Ahi*Wlo + Alo*Whi (fp32 accum); fp16 h out.
// Epilogue computes per-column-slice partial dots h·a_src, h·a_dst from fp32 regs.
#define SST 40   // smem row stride in bf16 elems (conflict-free for ldmatrix)

template <int K, int LAYER>
__global__ __launch_bounds__(256) void mma_gemm_kernel(const float* __restrict__ a_src,
                                                       const float* __restrict__ a_dst) {
    __shared__ __align__(16) __nv_bfloat16 sA[2][128 * SST];
    __shared__ __align__(16) __nv_bfloat16 sB[2][128 * SST];
    __shared__ float sas[128], sad[128], sds[128], sdd[128];

    const __nv_bfloat16* __restrict__ Ahi = g_ahi;
    const __nv_bfloat16* __restrict__ Alo = g_alo;
    const __nv_bfloat16* __restrict__ Whi = (LAYER == 1) ? g_w1hi : g_w2hi;
    const __nv_bfloat16* __restrict__ Wlo = (LAYER == 1) ? g_w1lo : g_w2lo;

    int tid = threadIdx.x;
    int wid = tid >> 5;
    int lane = tid & 31;
    int bm = blockIdx.x * 128;
    int bn = blockIdx.y * 128;
    int ny = blockIdx.y;
    int wm = (wid & 1) * 64;
    int wn = (wid >> 1) * 32;

    if (tid < 128) {
        sas[tid] = a_src[bn + tid];
        sad[tid] = a_dst[bn + tid];
        sds[tid] = 0.f;
        sdd[tid] = 0.f;
    }

    float acc[4][4][4];
    #pragma unroll
    for (int a = 0; a < 4; a++)
        #pragma unroll
        for (int b = 0; b < 4; b++)
            #pragma unroll
            for (int c = 0; c < 4; c++) acc[a][b][c] = 0.f;

    uint32_t aHb = smem_u32(&sA[0][0]);
    uint32_t aLb = smem_u32(&sA[1][0]);
    uint32_t bHb = smem_u32(&sB[0][0]);
    uint32_t bLb = smem_u32(&sB[1][0]);

    int a_row = wm + (lane & 15);
    int a_k8  = (lane >> 4) << 3;
    int b_row = wn + (lane & 7) + ((lane >> 4) << 3);
    int b_k8  = ((lane >> 3) & 1) << 3;

    for (int k0 = 0; k0 < K; k0 += 32) {
        #pragma unroll
        for (int it = 0; it < 2; it++) {
            int idx = tid + it * 256;
            int r = idx >> 2;
            int q = (idx & 3) << 3;
            int row = bm + r;
            uint4 vh = make_uint4(0u, 0u, 0u, 0u);
            uint4 vl = make_uint4(0u, 0u, 0u, 0u);
            if (row < NN) {
                vh = *(const uint4*)&Ahi[(size_t)row * K + k0 + q];
                vl = *(const uint4*)&Alo[(size_t)row * K + k0 + q];
            }
            *(uint4*)&sA[0][r * SST + q] = vh;
            *(uint4*)&sA[1][r * SST + q] = vl;
            *(uint4*)&sB[0][r * SST + q] = *(const uint4*)&Whi[(size_t)(bn + r) * K + k0 + q];
            *(uint4*)&sB[1][r * SST + q] = *(const uint4*)&Wlo[(size_t)(bn + r) * K + k0 + q];
        }
        __syncthreads();

        #pragma unroll
        for (int ks = 0; ks < 2; ks++) {
            int kk = ks * 16;
            uint32_t aH[4][4], aL[4][4], bH[2][4], bL[2][4];
            #pragma unroll
            for (int mt = 0; mt < 4; mt++) {
                uint32_t off = (uint32_t)(((a_row + mt * 16) * SST + kk + a_k8) * 2);
                LDSM4(aH[mt], aHb + off);
                LDSM4(aL[mt], aLb + off);
            }
            #pragma unroll
            for (int bt = 0; bt < 2; bt++) {
                uint32_t off = (uint32_t)(((b_row + bt * 16) * SST + kk + b_k8) * 2);
                LDSM4(bH[bt], bHb + off);
                LDSM4(bL[bt], bLb + off);
            }
            #pragma unroll
            for (int mt = 0; mt < 4; mt++) {
                #pragma unroll
                for (int nt = 0; nt < 4; nt++) {
                    int bt = nt >> 1;
                    int sb = (nt & 1) * 2;
                    MMA_BF16(acc[mt][nt], aH[mt], bH[bt][sb], bH[bt][sb + 1]);
                    MMA_BF16(acc[mt][nt], aH[mt], bL[bt][sb], bL[bt][sb + 1]);
                    MMA_BF16(acc[mt][nt], aL[mt], bH[bt][sb], bH[bt][sb + 1]);
                }
            }
        }
        __syncthreads();
    }

    // ---- epilogue: h -> fp16, fused partial dots from fp32 regs ----
    int gid = lane >> 2;
    int tig = lane & 3;
    #pragma unroll
    for (int mt = 0; mt < 4; mt++) {
        float ds0 = 0.f, ds1 = 0.f, dd0 = 0.f, dd1 = 0.f;
        #pragma unroll
        for (int nt = 0; nt < 4; nt++) {
            int cl = wn + nt * 8 + tig * 2;
            int row0 = bm + wm + mt * 16 + gid;
            int col = bn + cl;
            if (row0 < NN)
                *(__half2*)&g_hf16[(size_t)row0 * CC + col] =
                    __floats2half2_rn(acc[mt][nt][0], acc[mt][nt][1]);
            int row1 = row0 + 8;
            if (row1 < NN)
                *(__half2*)&g_hf16[(size_t)row1 * CC + col] =
                    __floats2half2_rn(acc[mt][nt][2], acc[mt][nt][3]);
            float as0 = sas[cl], as1 = sas[cl + 1];
            float ad0 = sad[cl], ad1 = sad[cl + 1];
            ds0 += acc[mt][nt][0] * as0 + acc[mt][nt][1] * as1;
            dd0 += acc[mt][nt][0] * ad0 + acc[mt][nt][1] * ad1;
            ds1 += acc[mt][nt][2] * as0 + acc[mt][nt][3] * as1;
            dd1 += acc[mt][nt][2] * ad0 + acc[mt][nt][3] * ad1;
        }
        #pragma unroll
        for (int o = 1; o <= 2; o <<= 1) {
            ds0 += __shfl_xor_sync(0xFFFFFFFFu, ds0, o);
            ds1 += __shfl_xor_sync(0xFFFFFFFFu, ds1, o);
            dd0 += __shfl_xor_sync(0xFFFFFFFFu, dd0, o);
            dd1 += __shfl_xor_sync(0xFFFFFFFFu, dd1, o);
        }
        if (tig == 0) {
            int lr = wm + mt * 16 + gid;
            atomicAdd(&sds[lr], ds0);
            atomicAdd(&sdd[lr], dd0);
            atomicAdd(&sds[lr + 8], ds1);
            atomicAdd(&sdd[lr + 8], dd1);
        }
    }
    __syncthreads();
    if (tid < 128) {
        int row = bm + tid;
        if (row < NN) {
            g_esp[ny * NN + row] = sds[tid];
            g_edp[ny * NN + row] = sdd[tid];
        }
    }
}

// ---------------- softmax + aggregate: warp per destination node ----------------
// Single pass (e bounded, softmax shift-invariant); fp16 gather; index prefetch.
template <bool FIRST>
__global__ void aggregate_kernel(const float* __restrict__ bias,
                                 float* __restrict__ out) {
    int w = (blockIdx.x * blockDim.x + threadIdx.x) >> 5;
    if (w >= NN) return;
    int lane = threadIdx.x & 31;

    float edst = g_edp[w] + g_edp[NN + w];
    int beg = g_rowptr[w];
    int end = g_rowptr[w + 1];

    float sum = 0.f;
    float acc[8] = {0.f, 0.f, 0.f, 0.f, 0.f, 0.f, 0.f, 0.f};

    int sN = g_col[beg];                      // deg >= 1 (self-loop)
    float eN = g_esp[sN] + g_esp[NN + sN];

    for (int j = beg; j < end; j++) {
        int s = sN;
        float es = eN;
        uint4 u = *(const uint4*)&g_hf16[(size_t)s * CC + lane * 8];
        if (j + 1 < end) {
            sN = g_col[j + 1];
            eN = g_esp[sN] + g_esp[NN + sN];
        }
        float e = es + edst;
        e = e > 0.f ? e : 0.2f * e;
        float p = __expf(e);
        sum += p;
        float2 f0 = __half22float2(*(__half2*)&u.x);
        float2 f1 = __half22float2(*(__half2*)&u.y);
        float2 f2 = __half22float2(*(__half2*)&u.z);
        float2 f3 = __half22float2(*(__half2*)&u.w);
        acc[0] += p * f0.x; acc[1] += p * f0.y;
        acc[2] += p * f1.x; acc[3] += p * f1.y;
        acc[4] += p * f2.x; acc[5] += p * f2.y;
        acc[6] += p * f3.x; acc[7] += p * f3.y;
    }

    float inv = 1.f / (sum + 1e-16f);
    int c = lane * 8;
    #pragma unroll
    for (int q = 0; q < 8; q++) {
        float v = acc[q] * inv + bias[c + q];
        v = fmaxf(v, 0.f);
        out[(size_t)w * 512 + (FIRST ? 0 : 256) + c + q] = v;
        if (FIRST) {
            __nv_bfloat16 h = __float2bfloat16(v);
            g_ahi[(size_t)w * CC + c + q] = h;
            g_alo[(size_t)w * CC + c + q] = __float2bfloat16(v - __bfloat162float(h));
        }
    }
}

// ---------------- launch ----------------
extern "C" void kernel_launch(void* const* d_in, const int* in_sizes, int n_in,
                              void* d_out, int out_size) {
    const float* x    = (const float*)d_in[0];
    const int*   ei   = (const int*)d_in[1];
    const float* W1   = (const float*)d_in[2];
    const float* a1s  = (const float*)d_in[3];
    const float* a1d  = (const float*)d_in[4];
    const float* b1   = (const float*)d_in[5];
    const float* W2   = (const float*)d_in[6];
    const float* a2s  = (const float*)d_in[7];
    const float* a2d  = (const float*)d_in[8];
    const float* b2   = (const float*)d_in[9];
    float* out = (float*)d_out;

    static cudaStream_t sB = nullptr;
    static cudaEvent_t evFork = nullptr, evJoin = nullptr;
    if (!sB) {
        cudaStreamCreateWithFlags(&sB, cudaStreamNonBlocking);
        cudaEventCreateWithFlags(&evFork, cudaEventDisableTiming);
        cudaEventCreateWithFlags(&evJoin, cudaEventDisableTiming);
    }
    cudaStream_t s0 = (cudaStream_t)0;

    dim3 ggrid((NN + 127) / 128, 2);
    int wnode_blocks = (NN + 7) / 8;

    // Submission order puts mma_gemm_kernel<128,1> at index 3 (ncu profiles #3).
    cudaEventRecord(evFork, s0);
    cudaStreamWaitEvent(sB, evFork, 0);

    prep_kernel<<<(NN * DD + 255) / 256, 256, 0, s0>>>(x, W1, W2);          // 0
    zero_deg_kernel<<<(NN + 255) / 256, 256, 0, sB>>>();                    // 1
    count_deg_kernel<<<(ETOT + 255) / 256, 256, 0, sB>>>(ei);               // 2
    mma_gemm_kernel<128, 1><<<ggrid, 256, 0, s0>>>(a1s, a1d);               // 3
    scan1_kernel<<<NB_SCAN, 1024, 0, sB>>>();                               // 4
    scan2_kernel<<<1, 64, 0, sB>>>();                                       // 5
    scan3_kernel<<<NB_SCAN, 1024, 0, sB>>>();                               // 6
    fill_kernel<<<(ETOT + 255) / 256, 256, 0, sB>>>(ei);                    // 7
    cudaEventRecord(evJoin, sB);

    cudaStreamWaitEvent(s0, evJoin, 0);
    aggregate_kernel<true><<<wnode_blocks, 256, 0, s0>>>(b1, out);          // 8

    mma_gemm_kernel<256, 2><<<ggrid, 256, 0, s0>>>(a2s, a2d);               // 9
    aggregate_kernel<false><<<wnode_blocks, 256, 0, s0>>>(b2, out);         // 10
}

// round 8
// speedup vs baseline: 2.1036x; 1.0096x over previous
#include <cuda_runtime.h>
#include <cuda_bf16.h>
#include <cuda_fp16.h>
#include <cstdint>
#include <math.h>

#define NN 50000
#define EE 500000
#define ETOT (EE + NN)
#define CC 256
#define DD 128
#define NB_SCAN 49   // ceil(50000/1024)

// ---------------- scratch (static __device__, no allocation) ----------------
__device__ __half g_hf16[(size_t)NN * CC];       // transformed features (fp16)
__device__ __nv_bfloat16 g_ahi[(size_t)NN * CC]; // split-bf16 A (hi)
__device__ __nv_bfloat16 g_alo[(size_t)NN * CC]; // split-bf16 A (lo)
__device__ __nv_bfloat16 g_w1hi[256 * 128], g_w1lo[256 * 128];
__device__ __nv_bfloat16 g_w2hi[256 * 256], g_w2lo[256 * 256];
__device__ float g_esrc[NN];
__device__ float g_edst[NN];
__device__ int   g_deg[NN];
__device__ int   g_rowptr[NN + 1];
__device__ int   g_cursor[NN];
__device__ int   g_col[ETOT];
__device__ int   g_bsum[NB_SCAN];

// ---------------- helpers ----------------
__device__ __forceinline__ uint32_t smem_u32(const void* p) {
    uint32_t a;
    asm("{ .reg .u64 t; cvta.to.shared.u64 t, %1; cvt.u32.u64 %0, t; }"
        : "=r"(a) : "l"(p));
    return a;
}

#define LDSM4(R, addr) \
    asm volatile("ldmatrix.sync.aligned.m8n8.x4.shared.b16 {%0,%1,%2,%3}, [%4];" \
                 : "=r"((R)[0]), "=r"((R)[1]), "=r"((R)[2]), "=r"((R)[3]) \
                 : "r"(addr))

#define MMA_BF16(d, a, b0, b1) \
    asm volatile("mma.sync.aligned.m16n8k16.row.col.f32.bf16.bf16.f32 " \
                 "{%0,%1,%2,%3},{%4,%5,%6,%7},{%8,%9},{%0,%1,%2,%3};" \
                 : "+f"((d)[0]), "+f"((d)[1]), "+f"((d)[2]), "+f"((d)[3]) \
                 : "r"((a)[0]), "r"((a)[1]), "r"((a)[2]), "r"((a)[3]), \
                   "r"(b0), "r"(b1))

#define CP16(smem_addr, gptr) \
    asm volatile("cp.async.cg.shared.global [%0], [%1], 16;" \
                 :: "r"(smem_addr), "l"(gptr))
#define CP_COMMIT() asm volatile("cp.async.commit_group;" ::: "memory")
#define CP_WAIT0()  asm volatile("cp.async.wait_group 0;" ::: "memory")

// ---------------- prep: split-bf16 conversions (fused) ----------------
__global__ void prep_kernel(const float* __restrict__ x,
                            const float* __restrict__ W1,
                            const float* __restrict__ W2) {
    int i = blockIdx.x * blockDim.x + threadIdx.x;
    if (i < NN * DD) {
        float v = x[i];
        __nv_bfloat16 h = __float2bfloat16(v);
        g_ahi[i] = h;
        g_alo[i] = __float2bfloat16(v - __bfloat162float(h));
    }
    if (i < 256 * 128) {
        float v = W1[i];
        __nv_bfloat16 h = __float2bfloat16(v);
        g_w1hi[i] = h;
        g_w1lo[i] = __float2bfloat16(v - __bfloat162float(h));
    }
    if (i < 256 * 256) {
        float v = W2[i];
        __nv_bfloat16 h = __float2bfloat16(v);
        g_w2hi[i] = h;
        g_w2lo[i] = __float2bfloat16(v - __bfloat162float(h));
    }
}

// ---------------- CSR build ----------------
__global__ void zero_deg_kernel() {
    int i = blockIdx.x * blockDim.x + threadIdx.x;
    if (i < NN) g_deg[i] = 0;
}

__global__ void count_deg_kernel(const int* __restrict__ ei) {
    int i = blockIdx.x * blockDim.x + threadIdx.x;
    if (i >= ETOT) return;
    int d = (i < EE) ? ei[EE + i] : (i - EE);
    atomicAdd(&g_deg[d], 1);
}

__global__ void scan1_kernel() {
    __shared__ int sh[1024];
    int t = threadIdx.x;
    int i = blockIdx.x * 1024 + t;
    int v = (i < NN) ? g_deg[i] : 0;
    sh[t] = v;
    __syncthreads();
    #pragma unroll
    for (int off = 1; off < 1024; off <<= 1) {
        int x = (t >= off) ? sh[t - off] : 0;
        __syncthreads();
        sh[t] += x;
        __syncthreads();
    }
    if (i < NN) g_rowptr[i + 1] = sh[t];
    if (t == 1023) g_bsum[blockIdx.x] = sh[1023];
}

__global__ void scan2_kernel() {
    __shared__ int sh[64];
    int t = threadIdx.x;
    int v = (t < NB_SCAN) ? g_bsum[t] : 0;
    sh[t] = v;
    __syncthreads();
    #pragma unroll
    for (int o = 1; o < 64; o <<= 1) {
        int x = (t >= o) ? sh[t - o] : 0;
        __syncthreads();
        sh[t] += x;
        __syncthreads();
    }
    if (t < NB_SCAN) g_bsum[t] = sh[t] - v;   // exclusive
}

__global__ void scan3_kernel() {
    int t = threadIdx.x;
    int i = blockIdx.x * 1024 + t;
    if (i < NN) {
        int r = g_rowptr[i + 1] + g_bsum[blockIdx.x];
        g_rowptr[i + 1] = r;
        if (i + 1 < NN) g_cursor[i + 1] = r;
        if (i == 0) { g_rowptr[0] = 0; g_cursor[0] = 0; }
    }
}

__global__ void fill_kernel(const int* __restrict__ ei) {
    int i = blockIdx.x * blockDim.x + threadIdx.x;
    if (i >= ETOT) return;
    int s, d;
    if (i < EE) { s = ei[i]; d = ei[EE + i]; }
    else        { s = i - EE; d = s; }
    int pos = atomicAdd(&g_cursor[d], 1);
    g_col[pos] = s;
}

// ---------------- HMMA GEMM + fused dots ----------------
// CTA tile 128x256 (full N), warp tile 64x64, BK=32, 8 warps (2m x 4n).
// cp.async 2-stage double buffer. Split-bf16: Ahi*Whi + Ahi*Wlo + Alo*Whi.
// Epilogue: fp16 h store + complete per-row e_src/e_dst dots.
#define SST 40                       // smem row stride (bf16), conflict-free
#define ABYTES (128 * SST * 2)       // 10240
#define BBYTES (256 * SST * 2)       // 20480
#define STAGE_B (2 * ABYTES + 2 * BBYTES)  // 61440
#define SM_TOTAL (2 * STAGE_B)       // 122880

template <int K, int LAYER>
__global__ __launch_bounds__(256) void mma_gemm_kernel(const float* __restrict__ a_src,
                                                       const float* __restrict__ a_dst) {
    extern __shared__ __align__(16) char dsm[];
    __shared__ float sas[256], sad[256], sds[128], sdd[128];

    const __nv_bfloat16* __restrict__ Ahi = g_ahi;
    const __nv_bfloat16* __restrict__ Alo = g_alo;
    const __nv_bfloat16* __restrict__ Whi = (LAYER == 1) ? g_w1hi : g_w2hi;
    const __nv_bfloat16* __restrict__ Wlo = (LAYER == 1) ? g_w1lo : g_w2lo;

    int tid = threadIdx.x;
    int wid = tid >> 5;
    int lane = tid & 31;
    int bm = blockIdx.x * 128;
    int wm = (wid & 1) * 64;
    int wn = (wid >> 1) * 64;

    uint32_t sbase = smem_u32(dsm);

    if (tid < 256) {
        sas[tid] = a_src[tid];
        sad[tid] = a_dst[tid];
    }
    if (tid < 128) { sds[tid] = 0.f; sdd[tid] = 0.f; }

    float acc[4][8][4];
    #pragma unroll
    for (int a = 0; a < 4; a++)
        #pragma unroll
        for (int b = 0; b < 8; b++)
            #pragma unroll
            for (int c = 0; c < 4; c++) acc[a][b][c] = 0.f;

    const int nchunk = K >> 5;

    // ---- async chunk loader ----
    auto load_chunk = [&](int c, int st) {
        int k0 = c * 32;
        uint32_t sA = sbase + st * STAGE_B;
        uint32_t sB = sA + 2 * ABYTES;
        #pragma unroll
        for (int it = 0; it < 2; it++) {
            int idx = tid + it * 256;
            int r = idx >> 2;
            int q = (idx & 3) << 3;
            int row = bm + r;
            if (row > NN - 1) row = NN - 1;
            uint32_t dst = sA + (uint32_t)(r * SST + q) * 2;
            CP16(dst, &Ahi[(size_t)row * K + k0 + q]);
            CP16(dst + ABYTES, &Alo[(size_t)row * K + k0 + q]);
        }
        #pragma unroll
        for (int it = 0; it < 4; it++) {
            int idx = tid + it * 256;
            int r = idx >> 2;
            int q = (idx & 3) << 3;
            uint32_t dst = sB + (uint32_t)(r * SST + q) * 2;
            CP16(dst, &Whi[(size_t)r * K + k0 + q]);
            CP16(dst + BBYTES, &Wlo[(size_t)r * K + k0 + q]);
        }
    };

    int a_row = wm + (lane & 15);
    int a_k8  = (lane >> 4) << 3;
    int b_row = wn + (lane & 7) + ((lane >> 4) << 3);
    int b_k8  = ((lane >> 3) & 1) << 3;

    load_chunk(0, 0);
    CP_COMMIT();

    for (int c = 0; c < nchunk; c++) {
        int st = c & 1;
        CP_WAIT0();
        __syncthreads();
        if (c + 1 < nchunk) {
            load_chunk(c + 1, (c + 1) & 1);
            CP_COMMIT();
        }

        uint32_t sA = sbase + st * STAGE_B;
        uint32_t sB = sA + 2 * ABYTES;

        #pragma unroll
        for (int ks = 0; ks < 2; ks++) {
            int kk = ks * 16;
            uint32_t aH[4][4], aL[4][4];
            #pragma unroll
            for (int mt = 0; mt < 4; mt++) {
                uint32_t off = (uint32_t)(((a_row + mt * 16) * SST + kk + a_k8) * 2);
                LDSM4(aH[mt], sA + off);
                LDSM4(aL[mt], sA + ABYTES + off);
            }
            #pragma unroll
            for (int half = 0; half < 2; half++) {
                uint32_t bH[2][4], bL[2][4];
                #pragma unroll
                for (int b2 = 0; b2 < 2; b2++) {
                    int bt = half * 2 + b2;
                    uint32_t off = (uint32_t)(((b_row + bt * 16) * SST + kk + b_k8) * 2);
                    LDSM4(bH[b2], sB + off);
                    LDSM4(bL[b2], sB + BBYTES + off);
                }
                #pragma unroll
                for (int mt = 0; mt < 4; mt++) {
                    #pragma unroll
                    for (int n4 = 0; n4 < 4; n4++) {
                        int nt = half * 4 + n4;
                        int b2 = n4 >> 1;
                        int sbi = (n4 & 1) * 2;
                        MMA_BF16(acc[mt][nt], aH[mt], bH[b2][sbi], bH[b2][sbi + 1]);
                        MMA_BF16(acc[mt][nt], aH[mt], bL[b2][sbi], bL[b2][sbi + 1]);
                        MMA_BF16(acc[mt][nt], aL[mt], bH[b2][sbi], bH[b2][sbi + 1]);
                    }
                }
            }
        }
        __syncthreads();
    }

    // ---- epilogue: fp16 h store + complete fused dots ----
    int gid = lane >> 2;
    int tig = lane & 3;
    #pragma unroll
    for (int mt = 0; mt < 4; mt++) {
        float ds0 = 0.f, ds1 = 0.f, dd0 = 0.f, dd1 = 0.f;
        #pragma unroll
        for (int nt = 0; nt < 8; nt++) {
            int col = wn + nt * 8 + tig * 2;
            int row0 = bm + wm + mt * 16 + gid;
            if (row0 < NN)
                *(__half2*)&g_hf16[(size_t)row0 * CC + col] =
                    __floats2half2_rn(acc[mt][nt][0], acc[mt][nt][1]);
            int row1 = row0 + 8;
            if (row1 < NN)
                *(__half2*)&g_hf16[(size_t)row1 * CC + col] =
                    __floats2half2_rn(acc[mt][nt][2], acc[mt][nt][3]);
            float as0 = sas[col], as1 = sas[col + 1];
            float ad0 = sad[col], ad1 = sad[col + 1];
            ds0 += acc[mt][nt][0] * as0 + acc[mt][nt][1] * as1;
            dd0 += acc[mt][nt][0] * ad0 + acc[mt][nt][1] * ad1;
            ds1 += acc[mt][nt][2] * as0 + acc[mt][nt][3] * as1;
            dd1 += acc[mt][nt][2] * ad0 + acc[mt][nt][3] * ad1;
        }
        #pragma unroll
        for (int o = 1; o <= 2; o <<= 1) {
            ds0 += __shfl_xor_sync(0xFFFFFFFFu, ds0, o);
            ds1 += __shfl_xor_sync(0xFFFFFFFFu, ds1, o);
            dd0 += __shfl_xor_sync(0xFFFFFFFFu, dd0, o);
            dd1 += __shfl_xor_sync(0xFFFFFFFFu, dd1, o);
        }
        if (tig == 0) {
            int lr = wm + mt * 16 + gid;
            atomicAdd(&sds[lr], ds0);
            atomicAdd(&sdd[lr], dd0);
            atomicAdd(&sds[lr + 8], ds1);
            atomicAdd(&sdd[lr + 8], dd1);
        }
    }
    __syncthreads();
    if (tid < 128) {
        int row = bm + tid;
        if (row < NN) {
            g_esrc[row] = sds[tid];
            g_edst[row] = sdd[tid];
        }
    }
}

// ---------------- softmax + aggregate: warp per destination node ----------------
template <bool FIRST>
__global__ void aggregate_kernel(const float* __restrict__ bias,
                                 float* __restrict__ out) {
    int w = (blockIdx.x * blockDim.x + threadIdx.x) >> 5;
    if (w >= NN) return;
    int lane = threadIdx.x & 31;

    float edst = g_edst[w];
    int beg = g_rowptr[w];
    int end = g_rowptr[w + 1];

    float sum = 0.f;
    float acc[8] = {0.f, 0.f, 0.f, 0.f, 0.f, 0.f, 0.f, 0.f};

    int sN = g_col[beg];                      // deg >= 1 (self-loop)
    float eN = g_esrc[sN];

    for (int j = beg; j < end; j++) {
        int s = sN;
        float es = eN;
        uint4 u = *(const uint4*)&g_hf16[(size_t)s * CC + lane * 8];
        if (j + 1 < end) {
            sN = g_col[j + 1];
            eN = g_esrc[sN];
        }
        float e = es + edst;
        e = e > 0.f ? e : 0.2f * e;
        float p = __expf(e);
        sum += p;
        float2 f0 = __half22float2(*(__half2*)&u.x);
        float2 f1 = __half22float2(*(__half2*)&u.y);
        float2 f2 = __half22float2(*(__half2*)&u.z);
        float2 f3 = __half22float2(*(__half2*)&u.w);
        acc[0] += p * f0.x; acc[1] += p * f0.y;
        acc[2] += p * f1.x; acc[3] += p * f1.y;
        acc[4] += p * f2.x; acc[5] += p * f2.y;
        acc[6] += p * f3.x; acc[7] += p * f3.y;
    }

    float inv = 1.f / (sum + 1e-16f);
    int c = lane * 8;
    #pragma unroll
    for (int q = 0; q < 8; q++) {
        float v = acc[q] * inv + bias[c + q];
        v = fmaxf(v, 0.f);
        out[(size_t)w * 512 + (FIRST ? 0 : 256) + c + q] = v;
        if (FIRST) {
            __nv_bfloat16 h = __float2bfloat16(v);
            g_ahi[(size_t)w * CC + c + q] = h;
            g_alo[(size_t)w * CC + c + q] = __float2bfloat16(v - __bfloat162float(h));
        }
    }
}

// ---------------- launch ----------------
extern "C" void kernel_launch(void* const* d_in, const int* in_sizes, int n_in,
                              void* d_out, int out_size) {
    const float* x    = (const float*)d_in[0];
    const int*   ei   = (const int*)d_in[1];
    const float* W1   = (const float*)d_in[2];
    const float* a1s  = (const float*)d_in[3];
    const float* a1d  = (const float*)d_in[4];
    const float* b1   = (const float*)d_in[5];
    const float* W2   = (const float*)d_in[6];
    const float* a2s  = (const float*)d_in[7];
    const float* a2d  = (const float*)d_in[8];
    const float* b2   = (const float*)d_in[9];
    float* out = (float*)d_out;

    static cudaStream_t strB = nullptr;
    static cudaEvent_t evFork = nullptr, evJoin = nullptr;
    if (!strB) {
        cudaStreamCreateWithFlags(&strB, cudaStreamNonBlocking);
        cudaEventCreateWithFlags(&evFork, cudaEventDisableTiming);
        cudaEventCreateWithFlags(&evJoin, cudaEventDisableTiming);
        cudaFuncSetAttribute(mma_gemm_kernel<128, 1>,
                             cudaFuncAttributeMaxDynamicSharedMemorySize, SM_TOTAL);
        cudaFuncSetAttribute(mma_gemm_kernel<256, 2>,
                             cudaFuncAttributeMaxDynamicSharedMemorySize, SM_TOTAL);
    }
    cudaStream_t s0 = (cudaStream_t)0;

    dim3 ggrid((NN + 127) / 128, 1);
    int wnode_blocks = (NN + 7) / 8;

    // Submission order keeps mma_gemm_kernel<128,1> at index 3 (ncu profiles #3).
    cudaEventRecord(evFork, s0);
    cudaStreamWaitEvent(strB, evFork, 0);

    prep_kernel<<<(NN * DD + 255) / 256, 256, 0, s0>>>(x, W1, W2);          // 0
    zero_deg_kernel<<<(NN + 255) / 256, 256, 0, strB>>>();                  // 1
    count_deg_kernel<<<(ETOT + 255) / 256, 256, 0, strB>>>(ei);             // 2
    mma_gemm_kernel<128, 1><<<ggrid, 256, SM_TOTAL, s0>>>(a1s, a1d);        // 3
    scan1_kernel<<<NB_SCAN, 1024, 0, strB>>>();                             // 4
    scan2_kernel<<<1, 64, 0, strB>>>();                                     // 5
    scan3_kernel<<<NB_SCAN, 1024, 0, strB>>>();                             // 6
    fill_kernel<<<(ETOT + 255) / 256, 256, 0, strB>>>(ei);                  // 7
    cudaEventRecord(evJoin, strB);

    cudaStreamWaitEvent(s0, evJoin, 0);
    aggregate_kernel<true><<<wnode_blocks, 256, 0, s0>>>(b1, out);          // 8

    mma_gemm_kernel<256, 2><<<ggrid, 256, SM_TOTAL, s0>>>(a2s, a2d);        // 9
    aggregate_kernel<false><<<wnode_blocks, 256, 0, s0>>>(b2, out);         // 10
}

// round 9
// speedup vs baseline: 2.9335x; 1.3945x over previous
#include <cuda_runtime.h>
#include <cuda_fp16.h>
#include <cstdint>
#include <math.h>

#define NN 50000
#define EE 500000
#define ETOT (EE + NN)
#define CC 256
#define DD 128
#define NB_SCAN 49   // ceil(50000/1024)

// ---------------- scratch (static __device__, no allocation) ----------------
__device__ __half g_hf16[(size_t)NN * CC];   // transformed features (fp16)
__device__ __half g_af16[(size_t)NN * CC];   // GEMM A operand (fp16)
__device__ __half g_w1f16[256 * 128];
__device__ __half g_w2f16[256 * 256];
__device__ float g_esrc[NN];
__device__ float g_edst[NN];
__device__ int   g_deg[NN];
__device__ int   g_rowptr[NN + 1];
__device__ int   g_cursor[NN];
__device__ int   g_col[ETOT];
__device__ int   g_bsum[NB_SCAN];

// ---------------- helpers ----------------
__device__ __forceinline__ uint32_t smem_u32(const void* p) {
    uint32_t a;
    asm("{ .reg .u64 t; cvta.to.shared.u64 t, %1; cvt.u32.u64 %0, t; }"
        : "=r"(a) : "l"(p));
    return a;
}

#define LDSM4(R, addr) \
    asm volatile("ldmatrix.sync.aligned.m8n8.x4.shared.b16 {%0,%1,%2,%3}, [%4];" \
                 : "=r"((R)[0]), "=r"((R)[1]), "=r"((R)[2]), "=r"((R)[3]) \
                 : "r"(addr))

#define MMA_FP16(d, a, b0, b1) \
    asm volatile("mma.sync.aligned.m16n8k16.row.col.f32.f16.f16.f32 " \
                 "{%0,%1,%2,%3},{%4,%5,%6,%7},{%8,%9},{%0,%1,%2,%3};" \
                 : "+f"((d)[0]), "+f"((d)[1]), "+f"((d)[2]), "+f"((d)[3]) \
                 : "r"((a)[0]), "r"((a)[1]), "r"((a)[2]), "r"((a)[3]), \
                   "r"(b0), "r"(b1))

#define CP16(smem_addr, gptr) \
    asm volatile("cp.async.cg.shared.global [%0], [%1], 16;" \
                 :: "r"(smem_addr), "l"(gptr))
#define CP_COMMIT() asm volatile("cp.async.commit_group;" ::: "memory")
#define CP_WAIT0()  asm volatile("cp.async.wait_group 0;" ::: "memory")

// ---------------- prep: fp16 conversions (fused) ----------------
__global__ void prep_kernel(const float* __restrict__ x,
                            const float* __restrict__ W1,
                            const float* __restrict__ W2) {
    int i = blockIdx.x * blockDim.x + threadIdx.x;
    if (i < NN * DD)    g_af16[i]  = __float2half(x[i]);
    if (i < 256 * 128)  g_w1f16[i] = __float2half(W1[i]);
    if (i < 256 * 256)  g_w2f16[i] = __float2half(W2[i]);
}

// ---------------- CSR build ----------------
__global__ void zero_deg_kernel() {
    int i = blockIdx.x * blockDim.x + threadIdx.x;
    if (i < NN) g_deg[i] = 0;
}

__global__ void count_deg_kernel(const int* __restrict__ ei) {
    int i = blockIdx.x * blockDim.x + threadIdx.x;
    if (i >= ETOT) return;
    int d = (i < EE) ? ei[EE + i] : (i - EE);
    atomicAdd(&g_deg[d], 1);
}

__global__ void scan1_kernel() {
    __shared__ int sh[1024];
    int t = threadIdx.x;
    int i = blockIdx.x * 1024 + t;
    int v = (i < NN) ? g_deg[i] : 0;
    sh[t] = v;
    __syncthreads();
    #pragma unroll
    for (int off = 1; off < 1024; off <<= 1) {
        int x = (t >= off) ? sh[t - off] : 0;
        __syncthreads();
        sh[t] += x;
        __syncthreads();
    }
    if (i < NN) g_rowptr[i + 1] = sh[t];
    if (t == 1023) g_bsum[blockIdx.x] = sh[1023];
}

__global__ void scan2_kernel() {
    __shared__ int sh[64];
    int t = threadIdx.x;
    int v = (t < NB_SCAN) ? g_bsum[t] : 0;
    sh[t] = v;
    __syncthreads();
    #pragma unroll
    for (int o = 1; o < 64; o <<= 1) {
        int x = (t >= o) ? sh[t - o] : 0;
        __syncthreads();
        sh[t] += x;
        __syncthreads();
    }
    if (t < NB_SCAN) g_bsum[t] = sh[t] - v;   // exclusive
}

__global__ void scan3_kernel() {
    int t = threadIdx.x;
    int i = blockIdx.x * 1024 + t;
    if (i < NN) {
        int r = g_rowptr[i + 1] + g_bsum[blockIdx.x];
        g_rowptr[i + 1] = r;
        if (i + 1 < NN) g_cursor[i + 1] = r;
        if (i == 0) { g_rowptr[0] = 0; g_cursor[0] = 0; }
    }
}

__global__ void fill_kernel(const int* __restrict__ ei) {
    int i = blockIdx.x * blockDim.x + threadIdx.x;
    if (i >= ETOT) return;
    int s, d;
    if (i < EE) { s = ei[i]; d = ei[EE + i]; }
    else        { s = i - EE; d = s; }
    int pos = atomicAdd(&g_cursor[d], 1);
    g_col[pos] = s;
}

// ---------------- HMMA GEMM (fp16 single product) + fused dots ----------------
// CTA tile 128x256 (full N), warp tile 64x64, BK=32, 8 warps (2m x 4n).
// cp.async 2-stage double buffer. Epilogue: fp16 h store + complete e dots.
#define SST 40                       // smem row stride (fp16), conflict-free
#define ABYTES (128 * SST * 2)       // 10240
#define BBYTES (256 * SST * 2)       // 20480
#define STAGE_B (ABYTES + BBYTES)    // 30720
#define SM_TOTAL (2 * STAGE_B)       // 61440

template <int K, int LAYER>
__global__ __launch_bounds__(256) void mma_gemm_kernel(const float* __restrict__ a_src,
                                                       const float* __restrict__ a_dst) {
    extern __shared__ __align__(16) char dsm[];
    __shared__ float sas[256], sad[256], sds[128], sdd[128];

    const __half* __restrict__ Af = g_af16;
    const __half* __restrict__ Wf = (LAYER == 1) ? g_w1f16 : g_w2f16;

    int tid = threadIdx.x;
    int wid = tid >> 5;
    int lane = tid & 31;
    int bm = blockIdx.x * 128;
    int wm = (wid & 1) * 64;
    int wn = (wid >> 1) * 64;

    uint32_t sbase = smem_u32(dsm);

    if (tid < 256) {
        sas[tid] = a_src[tid];
        sad[tid] = a_dst[tid];
    }
    if (tid < 128) { sds[tid] = 0.f; sdd[tid] = 0.f; }

    float acc[4][8][4];
    #pragma unroll
    for (int a = 0; a < 4; a++)
        #pragma unroll
        for (int b = 0; b < 8; b++)
            #pragma unroll
            for (int c = 0; c < 4; c++) acc[a][b][c] = 0.f;

    const int nchunk = K >> 5;

    auto load_chunk = [&](int c, int st) {
        int k0 = c * 32;
        uint32_t sA = sbase + st * STAGE_B;
        uint32_t sB = sA + ABYTES;
        #pragma unroll
        for (int it = 0; it < 2; it++) {
            int idx = tid + it * 256;
            int r = idx >> 2;
            int q = (idx & 3) << 3;
            int row = bm + r;
            if (row > NN - 1) row = NN - 1;
            CP16(sA + (uint32_t)(r * SST + q) * 2, &Af[(size_t)row * K + k0 + q]);
        }
        #pragma unroll
        for (int it = 0; it < 4; it++) {
            int idx = tid + it * 256;
            int r = idx >> 2;
            int q = (idx & 3) << 3;
            CP16(sB + (uint32_t)(r * SST + q) * 2, &Wf[(size_t)r * K + k0 + q]);
        }
    };

    int a_row = wm + (lane & 15);
    int a_k8  = (lane >> 4) << 3;
    int b_row = wn + (lane & 7) + ((lane >> 4) << 3);
    int b_k8  = ((lane >> 3) & 1) << 3;

    load_chunk(0, 0);
    CP_COMMIT();

    for (int c = 0; c < nchunk; c++) {
        int st = c & 1;
        CP_WAIT0();
        __syncthreads();
        if (c + 1 < nchunk) {
            load_chunk(c + 1, (c + 1) & 1);
            CP_COMMIT();
        }

        uint32_t sA = sbase + st * STAGE_B;
        uint32_t sB = sA + ABYTES;

        #pragma unroll
        for (int ks = 0; ks < 2; ks++) {
            int kk = ks * 16;
            uint32_t aF[4][4];
            #pragma unroll
            for (int mt = 0; mt < 4; mt++) {
                uint32_t off = (uint32_t)(((a_row + mt * 16) * SST + kk + a_k8) * 2);
                LDSM4(aF[mt], sA + off);
            }
            uint32_t bF[4][4];
            #pragma unroll
            for (int bt = 0; bt < 4; bt++) {
                uint32_t off = (uint32_t)(((b_row + bt * 16) * SST + kk + b_k8) * 2);
                LDSM4(bF[bt], sB + off);
            }
            #pragma unroll
            for (int mt = 0; mt < 4; mt++) {
                #pragma unroll
                for (int nt = 0; nt < 8; nt++) {
                    int bt = nt >> 1;
                    int sbi = (nt & 1) * 2;
                    MMA_FP16(acc[mt][nt], aF[mt], bF[bt][sbi], bF[bt][sbi + 1]);
                }
            }
        }
        __syncthreads();
    }

    // ---- epilogue: fp16 h store + complete fused dots ----
    int gid = lane >> 2;
    int tig = lane & 3;
    #pragma unroll
    for (int mt = 0; mt < 4; mt++) {
        float ds0 = 0.f, ds1 = 0.f, dd0 = 0.f, dd1 = 0.f;
        #pragma unroll
        for (int nt = 0; nt < 8; nt++) {
            int col = wn + nt * 8 + tig * 2;
            int row0 = bm + wm + mt * 16 + gid;
            if (row0 < NN)
                *(__half2*)&g_hf16[(size_t)row0 * CC + col] =
                    __floats2half2_rn(acc[mt][nt][0], acc[mt][nt][1]);
            int row1 = row0 + 8;
            if (row1 < NN)
                *(__half2*)&g_hf16[(size_t)row1 * CC + col] =
                    __floats2half2_rn(acc[mt][nt][2], acc[mt][nt][3]);
            float as0 = sas[col], as1 = sas[col + 1];
            float ad0 = sad[col], ad1 = sad[col + 1];
            ds0 += acc[mt][nt][0] * as0 + acc[mt][nt][1] * as1;
            dd0 += acc[mt][nt][0] * ad0 + acc[mt][nt][1] * ad1;
            ds1 += acc[mt][nt][2] * as0 + acc[mt][nt][3] * as1;
            dd1 += acc[mt][nt][2] * ad0 + acc[mt][nt][3] * ad1;
        }
        #pragma unroll
        for (int o = 1; o <= 2; o <<= 1) {
            ds0 += __shfl_xor_sync(0xFFFFFFFFu, ds0, o);
            ds1 += __shfl_xor_sync(0xFFFFFFFFu, ds1, o);
            dd0 += __shfl_xor_sync(0xFFFFFFFFu, dd0, o);
            dd1 += __shfl_xor_sync(0xFFFFFFFFu, dd1, o);
        }
        if (tig == 0) {
            int lr = wm + mt * 16 + gid;
            atomicAdd(&sds[lr], ds0);
            atomicAdd(&sdd[lr], dd0);
            atomicAdd(&sds[lr + 8], ds1);
            atomicAdd(&sdd[lr + 8], dd1);
        }
    }
    __syncthreads();
    if (tid < 128) {
        int row = bm + tid;
        if (row < NN) {
            g_esrc[row] = sds[tid];
            g_edst[row] = sdd[tid];
        }
    }
}

// ---------------- softmax + aggregate: warp per destination node ----------------
template <bool FIRST>
__global__ void aggregate_kernel(const float* __restrict__ bias,
                                 float* __restrict__ out) {
    int w = (blockIdx.x * blockDim.x + threadIdx.x) >> 5;
    if (w >= NN) return;
    int lane = threadIdx.x & 31;

    float edst = g_edst[w];
    int beg = g_rowptr[w];
    int end = g_rowptr[w + 1];

    float sum = 0.f;
    float acc[8] = {0.f, 0.f, 0.f, 0.f, 0.f, 0.f, 0.f, 0.f};

    int sN = g_col[beg];                      // deg >= 1 (self-loop)
    float eN = g_esrc[sN];

    for (int j = beg; j < end; j++) {
        int s = sN;
        float es = eN;
        uint4 u = *(const uint4*)&g_hf16[(size_t)s * CC + lane * 8];
        if (j + 1 < end) {
            sN = g_col[j + 1];
            eN = g_esrc[sN];
        }
        float e = es + edst;
        e = e > 0.f ? e : 0.2f * e;
        float p = __expf(e);
        sum += p;
        float2 f0 = __half22float2(*(__half2*)&u.x);
        float2 f1 = __half22float2(*(__half2*)&u.y);
        float2 f2 = __half22float2(*(__half2*)&u.z);
        float2 f3 = __half22float2(*(__half2*)&u.w);
        acc[0] += p * f0.x; acc[1] += p * f0.y;
        acc[2] += p * f1.x; acc[3] += p * f1.y;
        acc[4] += p * f2.x; acc[5] += p * f2.y;
        acc[6] += p * f3.x; acc[7] += p * f3.y;
    }

    float inv = 1.f / (sum + 1e-16f);
    int c = lane * 8;
    #pragma unroll
    for (int q = 0; q < 8; q++) {
        float v = acc[q] * inv + bias[c + q];
        v = fmaxf(v, 0.f);
        out[(size_t)w * 512 + (FIRST ? 0 : 256) + c + q] = v;
        if (FIRST)
            g_af16[(size_t)w * CC + c + q] = __float2half(v);
    }
}

// ---------------- launch ----------------
extern "C" void kernel_launch(void* const* d_in, const int* in_sizes, int n_in,
                              void* d_out, int out_size) {
    const float* x    = (const float*)d_in[0];
    const int*   ei   = (const int*)d_in[1];
    const float* W1   = (const float*)d_in[2];
    const float* a1s  = (const float*)d_in[3];
    const float* a1d  = (const float*)d_in[4];
    const float* b1   = (const float*)d_in[5];
    const float* W2   = (const float*)d_in[6];
    const float* a2s  = (const float*)d_in[7];
    const float* a2d  = (const float*)d_in[8];
    const float* b2   = (const float*)d_in[9];
    float* out = (float*)d_out;

    static cudaStream_t strB = nullptr;
    static cudaEvent_t evFork = nullptr, evJoin = nullptr;
    if (!strB) {
        cudaStreamCreateWithFlags(&strB, cudaStreamNonBlocking);
        cudaEventCreateWithFlags(&evFork, cudaEventDisableTiming);
        cudaEventCreateWithFlags(&evJoin, cudaEventDisableTiming);
        cudaFuncSetAttribute(mma_gemm_kernel<128, 1>,
                             cudaFuncAttributeMaxDynamicSharedMemorySize, SM_TOTAL);
        cudaFuncSetAttribute(mma_gemm_kernel<256, 2>,
                             cudaFuncAttributeMaxDynamicSharedMemorySize, SM_TOTAL);
    }
    cudaStream_t s0 = (cudaStream_t)0;

    dim3 ggrid((NN + 127) / 128, 1);
    int wnode_blocks = (NN + 7) / 8;

    // Submission order keeps mma_gemm_kernel<128,1> at index 3 (ncu profiles #3).
    cudaEventRecord(evFork, s0);
    cudaStreamWaitEvent(strB, evFork, 0);

    prep_kernel<<<(NN * DD + 255) / 256, 256, 0, s0>>>(x, W1, W2);          // 0
    zero_deg_kernel<<<(NN + 255) / 256, 256, 0, strB>>>();                  // 1
    count_deg_kernel<<<(ETOT + 255) / 256, 256, 0, strB>>>(ei);             // 2
    mma_gemm_kernel<128, 1><<<ggrid, 256, SM_TOTAL, s0>>>(a1s, a1d);        // 3
    scan1_kernel<<<NB_SCAN, 1024, 0, strB>>>();                             // 4
    scan2_kernel<<<1, 64, 0, strB>>>();                                     // 5
    scan3_kernel<<<NB_SCAN, 1024, 0, strB>>>();                             // 6
    fill_kernel<<<(ETOT + 255) / 256, 256, 0, strB>>>(ei);                  // 7
    cudaEventRecord(evJoin, strB);

    cudaStreamWaitEvent(s0, evJoin, 0);
    aggregate_kernel<true><<<wnode_blocks, 256, 0, s0>>>(b1, out);          // 8

    mma_gemm_kernel<256, 2><<<ggrid, 256, SM_TOTAL, s0>>>(a2s, a2d);        // 9
    aggregate_kernel<false><<<wnode_blocks, 256, 0, s0>>>(b2, out);         // 10
}